// round 10
// baseline (speedup 1.0000x reference)
#include <cuda_runtime.h>
#include <cuda_fp16.h>

#define N_NODES   100000
#define E_EDGES   1600000
#define H_DIM     128
#define L_LAYERS  4
#define C_CLASSES 12
#define G_GRAPHS  512
#define BN_EPS    1e-5f

#define SCAN_T    1024
#define CHUNK     ((N_NODES + SCAN_T - 1) / SCAN_T)   // 98

// smem strides (in uint32 units) chosen for conflict-free fragment loads
#define W_STRIDE  136
#define A_STRIDE  132

#define CVT_TF32(o, x) asm("cvt.rna.tf32.f32 %0, %1;" : "=r"(o) : "f"(x))
#define MMA_TF32(d, a0, a1, a2, a3, b0, b1) \
    asm("mma.sync.aligned.m16n8k8.row.col.f32.tf32.tf32.f32 " \
        "{%0,%1,%2,%3},{%4,%5,%6,%7},{%8,%9},{%0,%1,%2,%3};" \
        : "+f"((d)[0]), "+f"((d)[1]), "+f"((d)[2]), "+f"((d)[3]) \
        : "r"(a0), "r"(a1), "r"(a2), "r"(a3), "r"(b0), "r"(b1))

// ---------------- device scratch (no allocation allowed) ----------------
__device__ __align__(128) float  g_h  [N_NODES * H_DIM];   // activations (fp32)
__device__ __align__(128) __half g_hwh[N_NODES * H_DIM];   // (h @ W) * dinv[row], fp16
__device__ __align__(128) float  g_dinv[N_NODES];
__device__ __align__(128) int    g_deg [N_NODES];
__device__ __align__(128) int    g_rowstart[N_NODES + 1];
__device__ __align__(128) int    g_cursor  [N_NODES];
__device__ __align__(128) int    g_csr_src [E_EDGES];
__device__ __align__(128) float  g_pool[G_GRAPHS * H_DIM];
__device__ __align__(128) int    g_cnt [G_GRAPHS];

// ---------------- zero / degree / dinv ----------------
__global__ void zero_kernel() {
    int i = blockIdx.x * blockDim.x + threadIdx.x;
    if (i < N_NODES)          g_deg[i] = 0;
    if (i < G_GRAPHS * H_DIM) g_pool[i] = 0.f;
    if (i < G_GRAPHS)         g_cnt[i] = 0;
}

__global__ void degree_kernel(const int* __restrict__ ei) {
    int e = blockIdx.x * blockDim.x + threadIdx.x;
    if (e < E_EDGES) atomicAdd(&g_deg[ei[E_EDGES + e]], 1);
}

__global__ void __launch_bounds__(SCAN_T) scan_kernel() {
    __shared__ int part[SCAN_T];
    int t  = threadIdx.x;
    int lo = t * CHUNK;
    int hi = min(lo + CHUNK, N_NODES);
    int s = 0;
    for (int i = lo; i < hi; i++) s += g_deg[i];
    part[t] = s;
    __syncthreads();
    for (int d = 1; d < SCAN_T; d <<= 1) {
        int v = (t >= d) ? part[t - d] : 0;
        __syncthreads();
        part[t] += v;
        __syncthreads();
    }
    int run = part[t] - s;
    for (int i = lo; i < hi; i++) {
        g_rowstart[i] = run;
        g_cursor[i]   = run;
        int dg = g_deg[i];
        g_dinv[i] = rsqrtf((float)dg + 1.0f);
        run += dg;
    }
    if (t == SCAN_T - 1) g_rowstart[N_NODES] = run;
}

__global__ void fill_csr_kernel(const int* __restrict__ ei) {
    int e = blockIdx.x * blockDim.x + threadIdx.x;
    if (e < E_EDGES) {
        int s = ei[e];
        int d = ei[E_EDGES + e];
        int pos = atomicAdd(&g_cursor[d], 1);
        g_csr_src[pos] = s;
    }
}

// ---------------- GEMM (tf32 mma.sync): [N,128] @ [128,128] ----------------
// CTA: 64 rows x 128 cols, 8 warps = 4(m) x 2(n), warp tile 16x64.
// mode 0: g_h   = relu(x @ W + bias)            (A = x param, fp32 out)
// mode 1: g_hwh = half((g_h @ W) * dinv[row])   (fp16 out)
__global__ void __launch_bounds__(256, 2) gemm_kernel(
    const float* __restrict__ A_in, const float* __restrict__ W,
    const float* __restrict__ bias, int mode)
{
    extern __shared__ unsigned int smu[];
    unsigned int* Ws = smu;                     // [128][W_STRIDE]
    unsigned int* As = smu + 128 * W_STRIDE;    // [64][A_STRIDE]

    const float* A = (mode == 0) ? A_in : g_h;
    int tid  = threadIdx.x;
    int row0 = blockIdx.x * 64;

    // load W (tf32-rounded): 4096 float4 items
    const float4* W4 = (const float4*)W;
#pragma unroll
    for (int i = 0; i < 16; i++) {
        int idx = tid + 256 * i;            // float4 index
        int k   = idx >> 5;
        int c4  = idx & 31;
        float4 w = W4[idx];
        unsigned int* dst = Ws + k * W_STRIDE + c4 * 4;
        unsigned int t0, t1, t2, t3;
        CVT_TF32(t0, w.x); CVT_TF32(t1, w.y); CVT_TF32(t2, w.z); CVT_TF32(t3, w.w);
        dst[0] = t0; dst[1] = t1; dst[2] = t2; dst[3] = t3;
    }

    // load A tile (64 x 128, tf32-rounded, zero-pad OOB rows)
#pragma unroll
    for (int i = 0; i < 8; i++) {
        int idx = tid + 256 * i;
        int r   = idx >> 5;
        int c4  = idx & 31;
        float4 v = make_float4(0.f, 0.f, 0.f, 0.f);
        if (row0 + r < N_NODES)
            v = ((const float4*)(A + (size_t)(row0 + r) * 128))[c4];
        unsigned int* dst = As + r * A_STRIDE + c4 * 4;
        unsigned int t0, t1, t2, t3;
        CVT_TF32(t0, v.x); CVT_TF32(t1, v.y); CVT_TF32(t2, v.z); CVT_TF32(t3, v.w);
        dst[0] = t0; dst[1] = t1; dst[2] = t2; dst[3] = t3;
    }
    __syncthreads();

    int warp = tid >> 5, lane = tid & 31;
    int wm = warp >> 1;           // 0..3  (m groups of 16 rows)
    int wn = warp & 1;            // 0..1  (n halves of 64 cols)
    int g  = lane >> 2;           // 0..7
    int t  = lane & 3;            // 0..3

    float acc[8][4];
#pragma unroll
    for (int nt = 0; nt < 8; nt++)
#pragma unroll
        for (int c = 0; c < 4; c++) acc[nt][c] = 0.f;

    const unsigned int* a_base = As + (wm * 16 + g) * A_STRIDE;
    const unsigned int* b_base = Ws + wn * 64 + g;

#pragma unroll 4
    for (int ks = 0; ks < 16; ks++) {
        int kc = ks * 8;
        unsigned int a0 = a_base[kc + t];
        unsigned int a1 = a_base[8 * A_STRIDE + kc + t];
        unsigned int a2 = a_base[kc + t + 4];
        unsigned int a3 = a_base[8 * A_STRIDE + kc + t + 4];
        const unsigned int* b0p = b_base + (kc + t) * W_STRIDE;
        const unsigned int* b1p = b_base + (kc + t + 4) * W_STRIDE;
#pragma unroll
        for (int nt = 0; nt < 8; nt++) {
            unsigned int b0 = b0p[nt * 8];
            unsigned int b1 = b1p[nt * 8];
            MMA_TF32(acc[nt], a0, a1, a2, a3, b0, b1);
        }
    }

    // epilogue: rows r0 = row0 + wm*16 + g, r1 = r0 + 8; cols = wn*64 + nt*8 + 2t
    int r0 = row0 + wm * 16 + g;
    int r1 = r0 + 8;
    if (mode == 0) {
#pragma unroll
        for (int nt = 0; nt < 8; nt++) {
            int col = wn * 64 + nt * 8 + 2 * t;
            float b0 = bias[col], b1 = bias[col + 1];
            if (r0 < N_NODES) {
                float2 o = make_float2(fmaxf(acc[nt][0] + b0, 0.f),
                                       fmaxf(acc[nt][1] + b1, 0.f));
                *(float2*)(g_h + (size_t)r0 * 128 + col) = o;
            }
            if (r1 < N_NODES) {
                float2 o = make_float2(fmaxf(acc[nt][2] + b0, 0.f),
                                       fmaxf(acc[nt][3] + b1, 0.f));
                *(float2*)(g_h + (size_t)r1 * 128 + col) = o;
            }
        }
    } else {
        float dv0 = (r0 < N_NODES) ? g_dinv[r0] : 0.f;
        float dv1 = (r1 < N_NODES) ? g_dinv[r1] : 0.f;
#pragma unroll
        for (int nt = 0; nt < 8; nt++) {
            int col = wn * 64 + nt * 8 + 2 * t;
            if (r0 < N_NODES) {
                __half2 h = __floats2half2_rn(acc[nt][0] * dv0, acc[nt][1] * dv0);
                *(__half2*)(g_hwh + (size_t)r0 * 128 + col) = h;
            }
            if (r1 < N_NODES) {
                __half2 h = __floats2half2_rn(acc[nt][2] * dv1, acc[nt][3] * dv1);
                *(__half2*)(g_hwh + (size_t)r1 * 128 + col) = h;
            }
        }
    }
}

// ---------------- fused aggregation + BN + ReLU (HALF-warp per dst node) ----------------
// Two nodes per warp: lanes 0-15 -> node 2w, lanes 16-31 -> node 2w+1.
// Each lane handles 8 features (one uint4 = 8 halves). Two independent gather
// chains per warp -> 2x memory-level parallelism vs warp-per-node.
__global__ void __launch_bounds__(256) agg_kernel(
    const float* __restrict__ cb,
    const float* __restrict__ gamma,
    const float* __restrict__ beta,
    const float* __restrict__ mean,
    const float* __restrict__ var,
    const int* __restrict__ batch, int last)
{
    unsigned gtid = blockIdx.x * blockDim.x + threadIdx.x;
    unsigned w    = gtid >> 5;
    int lane      = threadIdx.x & 31;
    int half      = lane >> 4;
    int lane16    = lane & 15;
    unsigned n    = w * 2 + half;
    if (n >= N_NODES) return;                      // N even: whole warp exits together
    unsigned hmask = half ? 0xffff0000u : 0x0000ffffu;

    float acc[8];
    {
        uint4 raw = ((const uint4*)(g_hwh + (size_t)n * 128))[lane16];
        float2 f0 = __half22float2(*(__half2*)&raw.x);
        float2 f1 = __half22float2(*(__half2*)&raw.y);
        float2 f2 = __half22float2(*(__half2*)&raw.z);
        float2 f3 = __half22float2(*(__half2*)&raw.w);
        acc[0] = f0.x; acc[1] = f0.y; acc[2] = f1.x; acc[3] = f1.y;
        acc[4] = f2.x; acc[5] = f2.y; acc[6] = f3.x; acc[7] = f3.y;
    }

    int start = g_rowstart[n];
    int end   = g_rowstart[n + 1];
    for (int base = start; base < end; base += 16) {
        int cnt = min(16, end - base);
        int src = (base + lane16 < end) ? g_csr_src[base + lane16] : 0;
#pragma unroll 4
        for (int j = 0; j < cnt; j++) {
            int s = __shfl_sync(hmask, src, j, 16);
            uint4 raw = __ldg((const uint4*)(g_hwh + (size_t)s * 128) + lane16);
            float2 f0 = __half22float2(*(__half2*)&raw.x);
            float2 f1 = __half22float2(*(__half2*)&raw.y);
            float2 f2 = __half22float2(*(__half2*)&raw.z);
            float2 f3 = __half22float2(*(__half2*)&raw.w);
            acc[0] += f0.x; acc[1] += f0.y; acc[2] += f1.x; acc[3] += f1.y;
            acc[4] += f2.x; acc[5] += f2.y; acc[6] += f3.x; acc[7] += f3.y;
        }
    }

    float dv = g_dinv[n];
    int c8   = lane16 * 8;
    float o[8];
#pragma unroll
    for (int i = 0; i < 8; i++) {
        float s = gamma[c8 + i] * rsqrtf(var[c8 + i] + BN_EPS);
        o[i] = fmaxf((acc[i] * dv + cb[c8 + i] - mean[c8 + i]) * s + beta[c8 + i], 0.f);
    }

    if (!last) {
        float4* dst = (float4*)(g_h + (size_t)n * 128 + c8);
        dst[0] = make_float4(o[0], o[1], o[2], o[3]);
        dst[1] = make_float4(o[4], o[5], o[6], o[7]);
    } else {
        int b = batch[n];
        float* dp = g_pool + (size_t)b * 128 + c8;
        asm volatile("red.global.add.v4.f32 [%0], {%1,%2,%3,%4};"
                     :: "l"(dp), "f"(o[0]), "f"(o[1]), "f"(o[2]), "f"(o[3]) : "memory");
        asm volatile("red.global.add.v4.f32 [%0], {%1,%2,%3,%4};"
                     :: "l"(dp + 4), "f"(o[4]), "f"(o[5]), "f"(o[6]), "f"(o[7]) : "memory");
        if (lane16 == 0) atomicAdd(&g_cnt[b], 1);
    }
}

// ---------------- MLP head: one block per graph ----------------
__global__ void mlp_kernel(const float* __restrict__ fc1w, const float* __restrict__ fc1b,
                           const float* __restrict__ fc2w, const float* __restrict__ fc2b,
                           float* __restrict__ out)
{
    __shared__ float gv[128];
    __shared__ float hid[64];
    int g = blockIdx.x;
    int t = threadIdx.x;           // 64 threads
    float cnt = fmaxf((float)g_cnt[g], 1.0f);
    float inv = 1.0f / cnt;
    gv[t]      = g_pool[g * 128 + t]      * inv;
    gv[t + 64] = g_pool[g * 128 + 64 + t] * inv;
    __syncthreads();
    float acc = fc1b[t];
#pragma unroll 8
    for (int k = 0; k < 128; k++) acc = fmaf(gv[k], fc1w[k * 64 + t], acc);
    hid[t] = fmaxf(acc, 0.f);
    __syncthreads();
    if (t < C_CLASSES) {
        float o = fc2b[t];
#pragma unroll
        for (int j = 0; j < 64; j++) o = fmaf(hid[j], fc2w[j * C_CLASSES + t], o);
        out[g * C_CLASSES + t] = o;
    }
}

__global__ void tail_kernel(float* __restrict__ out, int out_size) {
    int i = G_GRAPHS * C_CLASSES + blockIdx.x * blockDim.x + threadIdx.x;
    if (i < out_size) out[i] = 0.f;
}

// ---------------- launcher ----------------
extern "C" void kernel_launch(void* const* d_in, const int* in_sizes, int n_in,
                              void* d_out, int out_size)
{
    const float* x      = (const float*)d_in[0];
    const int*   ei     = (const int*)d_in[1];
    const int*   batch  = (const int*)d_in[2];
    const float* w_in   = (const float*)d_in[3];
    const float* b_in   = (const float*)d_in[4];
    const float* conv_w = (const float*)d_in[5];
    const float* conv_b = (const float*)d_in[6];
    const float* bn_g   = (const float*)d_in[7];
    const float* bn_b   = (const float*)d_in[8];
    const float* bn_m   = (const float*)d_in[9];
    const float* bn_v   = (const float*)d_in[10];
    const float* fc1w   = (const float*)d_in[11];
    const float* fc1b   = (const float*)d_in[12];
    const float* fc2w   = (const float*)d_in[13];
    const float* fc2b   = (const float*)d_in[14];
    float*       out    = (float*)d_out;

    const int SMEM = (128 * W_STRIDE + 64 * A_STRIDE) * 4;   // 103424 B
    cudaFuncSetAttribute(gemm_kernel, cudaFuncAttributeMaxDynamicSharedMemorySize, SMEM);

    zero_kernel    <<<(N_NODES + 255) / 256, 256>>>();
    degree_kernel  <<<(E_EDGES + 255) / 256, 256>>>(ei);
    scan_kernel    <<<1, SCAN_T>>>();
    fill_csr_kernel<<<(E_EDGES + 255) / 256, 256>>>(ei);

    // input projection
    gemm_kernel<<<(N_NODES + 63) / 64, 256, SMEM>>>(x, w_in, b_in, 0);

    // agg: half-warp per node -> N/2 warps
    const unsigned agg_blocks = (((N_NODES + 1) / 2) * 32u + 255) / 256;

    for (int l = 0; l < L_LAYERS; l++) {
        gemm_kernel<<<(N_NODES + 63) / 64, 256, SMEM>>>(nullptr, conv_w + (size_t)l * 128 * 128, nullptr, 1);
        agg_kernel <<<agg_blocks, 256>>>(conv_b + l * 128,
                                         bn_g + l * 128, bn_b + l * 128,
                                         bn_m + l * 128, bn_v + l * 128,
                                         batch, (l == L_LAYERS - 1) ? 1 : 0);
    }

    mlp_kernel<<<G_GRAPHS, 64>>>(fc1w, fc1b, fc2w, fc2b, out);

    int tail = out_size - G_GRAPHS * C_CLASSES;
    if (tail > 0) tail_kernel<<<(tail + 255) / 256, 256>>>(out, out_size);
}

// round 11
// speedup vs baseline: 1.4069x; 1.4069x over previous
#include <cuda_runtime.h>
#include <cuda_fp16.h>

#define N_NODES   100000
#define E_EDGES   1600000
#define H_DIM     128
#define L_LAYERS  4
#define C_CLASSES 12
#define G_GRAPHS  512
#define BN_EPS    1e-5f
#define NB        ((N_NODES + 255) / 256)   // 391 blocks

// smem strides (in uint32 units) chosen for conflict-free fragment loads
#define W_STRIDE  136
#define A_STRIDE  132

#define CVT_TF32(o, x) asm("cvt.rna.tf32.f32 %0, %1;" : "=r"(o) : "f"(x))
#define MMA_TF32(d, a0, a1, a2, a3, b0, b1) \
    asm("mma.sync.aligned.m16n8k8.row.col.f32.tf32.tf32.f32 " \
        "{%0,%1,%2,%3},{%4,%5,%6,%7},{%8,%9},{%0,%1,%2,%3};" \
        : "+f"((d)[0]), "+f"((d)[1]), "+f"((d)[2]), "+f"((d)[3]) \
        : "r"(a0), "r"(a1), "r"(a2), "r"(a3), "r"(b0), "r"(b1))

// ---------------- device scratch (no allocation allowed) ----------------
__device__ __align__(128) __half g_hh [N_NODES * H_DIM];   // activations, fp16
__device__ __align__(128) __half g_hwh[N_NODES * H_DIM];   // (h @ W) * dinv[row], fp16
__device__ __align__(128) float  g_dinv[N_NODES];
__device__ __align__(128) int    g_deg [N_NODES];
__device__ __align__(128) int    g_blocksum[512];
__device__ __align__(128) int    g_blockoff[512];
__device__ __align__(128) int    g_rowstart[N_NODES + 1];
__device__ __align__(128) int    g_cursor  [N_NODES];
__device__ __align__(128) int    g_csr_src [E_EDGES];
__device__ __align__(128) float  g_pool[G_GRAPHS * H_DIM];
__device__ __align__(128) int    g_cnt [G_GRAPHS];

// ---------------- preproc ----------------
__global__ void zero_kernel() {
    int i = blockIdx.x * blockDim.x + threadIdx.x;
    if (i < N_NODES)          g_deg[i] = 0;
    if (i < G_GRAPHS * H_DIM) g_pool[i] = 0.f;
    if (i < G_GRAPHS)         g_cnt[i] = 0;
}

__global__ void degree_kernel(const int* __restrict__ ei) {
    int e4 = blockIdx.x * blockDim.x + threadIdx.x;
    if (e4 < E_EDGES / 4) {
        int4 d = ((const int4*)(ei + E_EDGES))[e4];
        atomicAdd(&g_deg[d.x], 1);
        atomicAdd(&g_deg[d.y], 1);
        atomicAdd(&g_deg[d.z], 1);
        atomicAdd(&g_deg[d.w], 1);
    }
}

// three-stage parallel exclusive scan of g_deg
__global__ void block_sum_kernel() {
    __shared__ int sd[256];
    int i = blockIdx.x * 256 + threadIdx.x;
    int v = (i < N_NODES) ? g_deg[i] : 0;
    sd[threadIdx.x] = v;
    __syncthreads();
#pragma unroll
    for (int s = 128; s > 0; s >>= 1) {
        if (threadIdx.x < s) sd[threadIdx.x] += sd[threadIdx.x + s];
        __syncthreads();
    }
    if (threadIdx.x == 0) g_blocksum[blockIdx.x] = sd[0];
}

__global__ void __launch_bounds__(512) scan_blocks_kernel() {
    __shared__ int part[512];
    int t = threadIdx.x;
    int v = (t < NB) ? g_blocksum[t] : 0;
    part[t] = v;
    __syncthreads();
#pragma unroll
    for (int d = 1; d < 512; d <<= 1) {
        int x = (t >= d) ? part[t - d] : 0;
        __syncthreads();
        part[t] += x;
        __syncthreads();
    }
    if (t < NB) g_blockoff[t] = part[t] - v;
    if (t == 511) g_rowstart[N_NODES] = part[511];
}

__global__ void fill_rowstart_kernel() {
    __shared__ int part[256];
    int i = blockIdx.x * 256 + threadIdx.x;
    int t = threadIdx.x;
    int dg = (i < N_NODES) ? g_deg[i] : 0;
    part[t] = dg;
    __syncthreads();
#pragma unroll
    for (int d = 1; d < 256; d <<= 1) {
        int x = (t >= d) ? part[t - d] : 0;
        __syncthreads();
        part[t] += x;
        __syncthreads();
    }
    if (i < N_NODES) {
        int rs = g_blockoff[blockIdx.x] + part[t] - dg;
        g_rowstart[i] = rs;
        g_cursor[i]   = rs;
        g_dinv[i]     = rsqrtf((float)dg + 1.0f);
    }
}

__global__ void fill_csr_kernel(const int* __restrict__ ei) {
    int e4 = blockIdx.x * blockDim.x + threadIdx.x;
    if (e4 < E_EDGES / 4) {
        int4 s = ((const int4*)ei)[e4];
        int4 d = ((const int4*)(ei + E_EDGES))[e4];
        g_csr_src[atomicAdd(&g_cursor[d.x], 1)] = s.x;
        g_csr_src[atomicAdd(&g_cursor[d.y], 1)] = s.y;
        g_csr_src[atomicAdd(&g_cursor[d.z], 1)] = s.z;
        g_csr_src[atomicAdd(&g_cursor[d.w], 1)] = s.w;
    }
}

// ---------------- GEMM (tf32 mma.sync): [N,128] @ [128,128] ----------------
// CTA: 64 rows x 128 cols, 8 warps = 4(m) x 2(n), warp tile 16x64.
// mode 0: g_hh  = half(relu(x @ W + bias))      (A = x param fp32)
// mode 1: g_hwh = half((g_hh @ W) * dinv[row])  (A = g_hh fp16)
__global__ void __launch_bounds__(256, 2) gemm_kernel(
    const float* __restrict__ A_in, const float* __restrict__ W,
    const float* __restrict__ bias, int mode)
{
    extern __shared__ unsigned int smu[];
    unsigned int* Ws = smu;                     // [128][W_STRIDE]
    unsigned int* As = smu + 128 * W_STRIDE;    // [64][A_STRIDE]

    int tid  = threadIdx.x;
    int row0 = blockIdx.x * 64;

    // load W (tf32-rounded): 4096 float4 items
    const float4* W4 = (const float4*)W;
#pragma unroll
    for (int i = 0; i < 16; i++) {
        int idx = tid + 256 * i;            // float4 index
        int k   = idx >> 5;
        int c4  = idx & 31;
        float4 w = W4[idx];
        unsigned int* dst = Ws + k * W_STRIDE + c4 * 4;
        unsigned int t0, t1, t2, t3;
        CVT_TF32(t0, w.x); CVT_TF32(t1, w.y); CVT_TF32(t2, w.z); CVT_TF32(t3, w.w);
        dst[0] = t0; dst[1] = t1; dst[2] = t2; dst[3] = t3;
    }

    if (mode == 0) {
        // A from fp32 param
#pragma unroll
        for (int i = 0; i < 8; i++) {
            int idx = tid + 256 * i;
            int r   = idx >> 5;
            int c4  = idx & 31;
            float4 v = make_float4(0.f, 0.f, 0.f, 0.f);
            if (row0 + r < N_NODES)
                v = ((const float4*)(A_in + (size_t)(row0 + r) * 128))[c4];
            unsigned int* dst = As + r * A_STRIDE + c4 * 4;
            unsigned int t0, t1, t2, t3;
            CVT_TF32(t0, v.x); CVT_TF32(t1, v.y); CVT_TF32(t2, v.z); CVT_TF32(t3, v.w);
            dst[0] = t0; dst[1] = t1; dst[2] = t2; dst[3] = t3;
        }
    } else {
        // A from g_hh fp16: 64 rows x 16 uint4 (8 halves each)
#pragma unroll
        for (int i = 0; i < 4; i++) {
            int idx = tid + 256 * i;          // uint4 index, 1024 total
            int r   = idx >> 4;
            int c16 = idx & 15;
            uint4 raw = make_uint4(0, 0, 0, 0);
            if (row0 + r < N_NODES)
                raw = ((const uint4*)(g_hh + (size_t)(row0 + r) * 128))[c16];
            unsigned int* dst = As + r * A_STRIDE + c16 * 8;
            float2 f; unsigned int tv;
            f = __half22float2(*(__half2*)&raw.x);
            CVT_TF32(tv, f.x); dst[0] = tv; CVT_TF32(tv, f.y); dst[1] = tv;
            f = __half22float2(*(__half2*)&raw.y);
            CVT_TF32(tv, f.x); dst[2] = tv; CVT_TF32(tv, f.y); dst[3] = tv;
            f = __half22float2(*(__half2*)&raw.z);
            CVT_TF32(tv, f.x); dst[4] = tv; CVT_TF32(tv, f.y); dst[5] = tv;
            f = __half22float2(*(__half2*)&raw.w);
            CVT_TF32(tv, f.x); dst[6] = tv; CVT_TF32(tv, f.y); dst[7] = tv;
        }
    }
    __syncthreads();

    int warp = tid >> 5, lane = tid & 31;
    int wm = warp >> 1;           // 0..3  (m groups of 16 rows)
    int wn = warp & 1;            // 0..1  (n halves of 64 cols)
    int g  = lane >> 2;           // 0..7
    int t  = lane & 3;            // 0..3

    float acc[8][4];
#pragma unroll
    for (int nt = 0; nt < 8; nt++)
#pragma unroll
        for (int c = 0; c < 4; c++) acc[nt][c] = 0.f;

    const unsigned int* a_base = As + (wm * 16 + g) * A_STRIDE;
    const unsigned int* b_base = Ws + wn * 64 + g;

#pragma unroll 4
    for (int ks = 0; ks < 16; ks++) {
        int kc = ks * 8;
        unsigned int a0 = a_base[kc + t];
        unsigned int a1 = a_base[8 * A_STRIDE + kc + t];
        unsigned int a2 = a_base[kc + t + 4];
        unsigned int a3 = a_base[8 * A_STRIDE + kc + t + 4];
        const unsigned int* b0p = b_base + (kc + t) * W_STRIDE;
        const unsigned int* b1p = b_base + (kc + t + 4) * W_STRIDE;
#pragma unroll
        for (int nt = 0; nt < 8; nt++) {
            unsigned int b0 = b0p[nt * 8];
            unsigned int b1 = b1p[nt * 8];
            MMA_TF32(acc[nt], a0, a1, a2, a3, b0, b1);
        }
    }

    // epilogue: rows r0 = row0 + wm*16 + g, r1 = r0 + 8; cols = wn*64 + nt*8 + 2t
    int r0 = row0 + wm * 16 + g;
    int r1 = r0 + 8;
    if (mode == 0) {
#pragma unroll
        for (int nt = 0; nt < 8; nt++) {
            int col = wn * 64 + nt * 8 + 2 * t;
            float b0 = bias[col], b1 = bias[col + 1];
            if (r0 < N_NODES) {
                __half2 h = __floats2half2_rn(fmaxf(acc[nt][0] + b0, 0.f),
                                              fmaxf(acc[nt][1] + b1, 0.f));
                *(__half2*)(g_hh + (size_t)r0 * 128 + col) = h;
            }
            if (r1 < N_NODES) {
                __half2 h = __floats2half2_rn(fmaxf(acc[nt][2] + b0, 0.f),
                                              fmaxf(acc[nt][3] + b1, 0.f));
                *(__half2*)(g_hh + (size_t)r1 * 128 + col) = h;
            }
        }
    } else {
        float dv0 = (r0 < N_NODES) ? g_dinv[r0] : 0.f;
        float dv1 = (r1 < N_NODES) ? g_dinv[r1] : 0.f;
#pragma unroll
        for (int nt = 0; nt < 8; nt++) {
            int col = wn * 64 + nt * 8 + 2 * t;
            if (r0 < N_NODES) {
                __half2 h = __floats2half2_rn(acc[nt][0] * dv0, acc[nt][1] * dv0);
                *(__half2*)(g_hwh + (size_t)r0 * 128 + col) = h;
            }
            if (r1 < N_NODES) {
                __half2 h = __floats2half2_rn(acc[nt][2] * dv1, acc[nt][3] * dv1);
                *(__half2*)(g_hwh + (size_t)r1 * 128 + col) = h;
            }
        }
    }
}

// ---------------- fused aggregation + BN + ReLU (half-warp per dst node) ----------------
__global__ void __launch_bounds__(256) agg_kernel(
    const float* __restrict__ cb,
    const float* __restrict__ gamma,
    const float* __restrict__ beta,
    const float* __restrict__ mean,
    const float* __restrict__ var,
    const int* __restrict__ batch, int last)
{
    unsigned gtid = blockIdx.x * blockDim.x + threadIdx.x;
    unsigned w    = gtid >> 5;
    int lane      = threadIdx.x & 31;
    int half      = lane >> 4;
    int lane16    = lane & 15;
    unsigned n    = w * 2 + half;
    if (n >= N_NODES) return;                      // N even: whole warp exits together
    unsigned hmask = half ? 0xffff0000u : 0x0000ffffu;

    float acc[8];
    {
        uint4 raw = ((const uint4*)(g_hwh + (size_t)n * 128))[lane16];
        float2 f0 = __half22float2(*(__half2*)&raw.x);
        float2 f1 = __half22float2(*(__half2*)&raw.y);
        float2 f2 = __half22float2(*(__half2*)&raw.z);
        float2 f3 = __half22float2(*(__half2*)&raw.w);
        acc[0] = f0.x; acc[1] = f0.y; acc[2] = f1.x; acc[3] = f1.y;
        acc[4] = f2.x; acc[5] = f2.y; acc[6] = f3.x; acc[7] = f3.y;
    }

    int start = g_rowstart[n];
    int end   = g_rowstart[n + 1];
    for (int base = start; base < end; base += 16) {
        int cnt = min(16, end - base);
        int src = (base + lane16 < end) ? g_csr_src[base + lane16] : 0;
#pragma unroll 4
        for (int j = 0; j < cnt; j++) {
            int s = __shfl_sync(hmask, src, j, 16);
            uint4 raw = __ldg((const uint4*)(g_hwh + (size_t)s * 128) + lane16);
            float2 f0 = __half22float2(*(__half2*)&raw.x);
            float2 f1 = __half22float2(*(__half2*)&raw.y);
            float2 f2 = __half22float2(*(__half2*)&raw.z);
            float2 f3 = __half22float2(*(__half2*)&raw.w);
            acc[0] += f0.x; acc[1] += f0.y; acc[2] += f1.x; acc[3] += f1.y;
            acc[4] += f2.x; acc[5] += f2.y; acc[6] += f3.x; acc[7] += f3.y;
        }
    }

    float dv = g_dinv[n];
    int c8   = lane16 * 8;
    float o[8];
#pragma unroll
    for (int i = 0; i < 8; i++) {
        float s = gamma[c8 + i] * rsqrtf(var[c8 + i] + BN_EPS);
        o[i] = fmaxf((acc[i] * dv + cb[c8 + i] - mean[c8 + i]) * s + beta[c8 + i], 0.f);
    }

    if (!last) {
        __half2 h0 = __floats2half2_rn(o[0], o[1]);
        __half2 h1 = __floats2half2_rn(o[2], o[3]);
        __half2 h2 = __floats2half2_rn(o[4], o[5]);
        __half2 h3 = __floats2half2_rn(o[6], o[7]);
        uint4 st;
        st.x = *(unsigned int*)&h0; st.y = *(unsigned int*)&h1;
        st.z = *(unsigned int*)&h2; st.w = *(unsigned int*)&h3;
        *((uint4*)(g_hh + (size_t)n * 128 + c8)) = st;
    } else {
        int b = batch[n];
        float* dp = g_pool + (size_t)b * 128 + c8;
        asm volatile("red.global.add.v4.f32 [%0], {%1,%2,%3,%4};"
                     :: "l"(dp), "f"(o[0]), "f"(o[1]), "f"(o[2]), "f"(o[3]) : "memory");
        asm volatile("red.global.add.v4.f32 [%0], {%1,%2,%3,%4};"
                     :: "l"(dp + 4), "f"(o[4]), "f"(o[5]), "f"(o[6]), "f"(o[7]) : "memory");
        if (lane16 == 0) atomicAdd(&g_cnt[b], 1);
    }
}

// ---------------- MLP head: one block per graph ----------------
__global__ void mlp_kernel(const float* __restrict__ fc1w, const float* __restrict__ fc1b,
                           const float* __restrict__ fc2w, const float* __restrict__ fc2b,
                           float* __restrict__ out)
{
    __shared__ float gv[128];
    __shared__ float hid[64];
    int g = blockIdx.x;
    int t = threadIdx.x;           // 64 threads
    float cnt = fmaxf((float)g_cnt[g], 1.0f);
    float inv = 1.0f / cnt;
    gv[t]      = g_pool[g * 128 + t]      * inv;
    gv[t + 64] = g_pool[g * 128 + 64 + t] * inv;
    __syncthreads();
    float acc = fc1b[t];
#pragma unroll 8
    for (int k = 0; k < 128; k++) acc = fmaf(gv[k], fc1w[k * 64 + t], acc);
    hid[t] = fmaxf(acc, 0.f);
    __syncthreads();
    if (t < C_CLASSES) {
        float o = fc2b[t];
#pragma unroll
        for (int j = 0; j < 64; j++) o = fmaf(hid[j], fc2w[j * C_CLASSES + t], o);
        out[g * C_CLASSES + t] = o;
    }
}

__global__ void tail_kernel(float* __restrict__ out, int out_size) {
    int i = G_GRAPHS * C_CLASSES + blockIdx.x * blockDim.x + threadIdx.x;
    if (i < out_size) out[i] = 0.f;
}

// ---------------- launcher ----------------
extern "C" void kernel_launch(void* const* d_in, const int* in_sizes, int n_in,
                              void* d_out, int out_size)
{
    const float* x      = (const float*)d_in[0];
    const int*   ei     = (const int*)d_in[1];
    const int*   batch  = (const int*)d_in[2];
    const float* w_in   = (const float*)d_in[3];
    const float* b_in   = (const float*)d_in[4];
    const float* conv_w = (const float*)d_in[5];
    const float* conv_b = (const float*)d_in[6];
    const float* bn_g   = (const float*)d_in[7];
    const float* bn_b   = (const float*)d_in[8];
    const float* bn_m   = (const float*)d_in[9];
    const float* bn_v   = (const float*)d_in[10];
    const float* fc1w   = (const float*)d_in[11];
    const float* fc1b   = (const float*)d_in[12];
    const float* fc2w   = (const float*)d_in[13];
    const float* fc2b   = (const float*)d_in[14];
    float*       out    = (float*)d_out;

    const int SMEM = (128 * W_STRIDE + 64 * A_STRIDE) * 4;   // 103424 B
    cudaFuncSetAttribute(gemm_kernel, cudaFuncAttributeMaxDynamicSharedMemorySize, SMEM);

    zero_kernel         <<<(N_NODES + 255) / 256, 256>>>();
    degree_kernel       <<<(E_EDGES / 4 + 255) / 256, 256>>>(ei);
    block_sum_kernel    <<<NB, 256>>>();
    scan_blocks_kernel  <<<1, 512>>>();
    fill_rowstart_kernel<<<NB, 256>>>();
    fill_csr_kernel     <<<(E_EDGES / 4 + 255) / 256, 256>>>(ei);

    // input projection
    gemm_kernel<<<(N_NODES + 63) / 64, 256, SMEM>>>(x, w_in, b_in, 0);

    // agg: half-warp per node -> N/2 warps
    const unsigned agg_blocks = (((N_NODES + 1) / 2) * 32u + 255) / 256;

    for (int l = 0; l < L_LAYERS; l++) {
        gemm_kernel<<<(N_NODES + 63) / 64, 256, SMEM>>>(nullptr, conv_w + (size_t)l * 128 * 128, nullptr, 1);
        agg_kernel <<<agg_blocks, 256>>>(conv_b + l * 128,
                                         bn_g + l * 128, bn_b + l * 128,
                                         bn_m + l * 128, bn_v + l * 128,
                                         batch, (l == L_LAYERS - 1) ? 1 : 0);
    }

    mlp_kernel<<<G_GRAPHS, 64>>>(fc1w, fc1b, fc2w, fc2b, out);

    int tail = out_size - G_GRAPHS * C_CLASSES;
    if (tail > 0) tail_kernel<<<(tail + 255) / 256, 256>>>(out, out_size);
}

// round 13
// speedup vs baseline: 1.6767x; 1.1918x over previous
#include <cuda_runtime.h>
#include <cuda_fp16.h>

#define N_NODES   100000
#define E_EDGES   1600000
#define H_DIM     128
#define L_LAYERS  4
#define C_CLASSES 12
#define G_GRAPHS  512
#define BN_EPS    1e-5f
#define NB        ((N_NODES + 255) / 256)   // 391 blocks

#define S_STRIDE  136   // smem stride in halves (272 B) -> conflict-free frags

#define MMA_F16(d, a0, a1, a2, a3, b0, b1) \
    asm("mma.sync.aligned.m16n8k16.row.col.f32.f16.f16.f32 " \
        "{%0,%1,%2,%3},{%4,%5,%6,%7},{%8,%9},{%0,%1,%2,%3};" \
        : "+f"((d)[0]), "+f"((d)[1]), "+f"((d)[2]), "+f"((d)[3]) \
        : "r"(a0), "r"(a1), "r"(a2), "r"(a3), "r"(b0), "r"(b1))

// ---------------- device scratch (no allocation allowed) ----------------
__device__ __align__(128) __half g_hh [N_NODES * H_DIM];   // activations, fp16
__device__ __align__(128) __half g_hwh[N_NODES * H_DIM];   // (h @ W) * dinv[row], fp16
__device__ __align__(128) __half g_wh [5 * H_DIM * H_DIM]; // weights, fp16, [mat][n][k] (transposed)
__device__ __align__(128) float  g_dinv[N_NODES];
__device__ __align__(128) int    g_deg [N_NODES];
__device__ __align__(128) int    g_blocksum[512];
__device__ __align__(128) int    g_blockoff[512];
__device__ __align__(128) int    g_rowstart[N_NODES + 1];
__device__ __align__(128) int    g_cursor  [N_NODES];
__device__ __align__(128) int    g_csr_src [E_EDGES];
__device__ __align__(128) float  g_pool[G_GRAPHS * H_DIM];
__device__ __align__(128) int    g_cnt [G_GRAPHS];

// ---------------- preproc ----------------
__global__ void zero_kernel() {
    int i = blockIdx.x * blockDim.x + threadIdx.x;
    if (i < N_NODES)          g_deg[i] = 0;
    if (i < G_GRAPHS * H_DIM) g_pool[i] = 0.f;
    if (i < G_GRAPHS)         g_cnt[i] = 0;
}

// convert + transpose weights: g_wh[m][n][k] = half(W_m[k][n])
__global__ void wconv_kernel(const float* __restrict__ w_in,
                             const float* __restrict__ conv_w) {
    int i = blockIdx.x * blockDim.x + threadIdx.x;     // 5*16384
    if (i >= 5 * 16384) return;
    int m = i >> 14;
    int r = i & 16383;
    int k = r >> 7;
    int n = r & 127;            // n inner -> coalesced source reads
    const float* src = (m == 0) ? w_in : conv_w + (size_t)(m - 1) * 16384;
    g_wh[(size_t)m * 16384 + n * 128 + k] = __float2half(src[k * 128 + n]);
}

__global__ void degree_kernel(const int* __restrict__ ei) {
    int e4 = blockIdx.x * blockDim.x + threadIdx.x;
    if (e4 < E_EDGES / 4) {
        int4 d = ((const int4*)(ei + E_EDGES))[e4];
        atomicAdd(&g_deg[d.x], 1);
        atomicAdd(&g_deg[d.y], 1);
        atomicAdd(&g_deg[d.z], 1);
        atomicAdd(&g_deg[d.w], 1);
    }
}

// three-stage parallel exclusive scan of g_deg
__global__ void block_sum_kernel() {
    __shared__ int sd[256];
    int i = blockIdx.x * 256 + threadIdx.x;
    int v = (i < N_NODES) ? g_deg[i] : 0;
    sd[threadIdx.x] = v;
    __syncthreads();
#pragma unroll
    for (int s = 128; s > 0; s >>= 1) {
        if (threadIdx.x < s) sd[threadIdx.x] += sd[threadIdx.x + s];
        __syncthreads();
    }
    if (threadIdx.x == 0) g_blocksum[blockIdx.x] = sd[0];
}

__global__ void __launch_bounds__(512) scan_blocks_kernel() {
    __shared__ int part[512];
    int t = threadIdx.x;
    int v = (t < NB) ? g_blocksum[t] : 0;
    part[t] = v;
    __syncthreads();
#pragma unroll
    for (int d = 1; d < 512; d <<= 1) {
        int x = (t >= d) ? part[t - d] : 0;
        __syncthreads();
        part[t] += x;
        __syncthreads();
    }
    if (t < NB) g_blockoff[t] = part[t] - v;
    if (t == 511) g_rowstart[N_NODES] = part[511];
}

__global__ void fill_rowstart_kernel() {
    __shared__ int part[256];
    int i = blockIdx.x * 256 + threadIdx.x;
    int t = threadIdx.x;
    int dg = (i < N_NODES) ? g_deg[i] : 0;
    part[t] = dg;
    __syncthreads();
#pragma unroll
    for (int d = 1; d < 256; d <<= 1) {
        int x = (t >= d) ? part[t - d] : 0;
        __syncthreads();
        part[t] += x;
        __syncthreads();
    }
    if (i < N_NODES) {
        int rs = g_blockoff[blockIdx.x] + part[t] - dg;
        g_rowstart[i] = rs;
        g_cursor[i]   = rs;
        g_dinv[i]     = rsqrtf((float)dg + 1.0f);
    }
}

__global__ void fill_csr_kernel(const int* __restrict__ ei) {
    int e4 = blockIdx.x * blockDim.x + threadIdx.x;
    if (e4 < E_EDGES / 4) {
        int4 s = ((const int4*)ei)[e4];
        int4 d = ((const int4*)(ei + E_EDGES))[e4];
        g_csr_src[atomicAdd(&g_cursor[d.x], 1)] = s.x;
        g_csr_src[atomicAdd(&g_cursor[d.y], 1)] = s.y;
        g_csr_src[atomicAdd(&g_cursor[d.z], 1)] = s.z;
        g_csr_src[atomicAdd(&g_cursor[d.w], 1)] = s.w;
    }
}

// ---------------- GEMM (fp16 mma m16n8k16): [N,128] @ [128,128] ----------------
// CTA: 64 rows x 128 cols, 8 warps = 4(m) x 2(n), warp tile 16x64.
// Weights taken from g_wh by index (device symbol must not be passed from host!).
// mode 0: g_hh  = half(relu(x @ W + bias))      (A = x param fp32)
// mode 1: g_hwh = half((g_hh @ W) * dinv[row])  (A = g_hh fp16, zero-copy)
__global__ void __launch_bounds__(256, 2) gemm_kernel(
    const float* __restrict__ A_in, int wmat,
    const float* __restrict__ bias, int mode)
{
    extern __shared__ __half smh[];
    __half* Ws = smh;                       // [n=128][k=128] stride S_STRIDE
    __half* As = smh + 128 * S_STRIDE;      // [r=64][k=128]  stride S_STRIDE

    const __half* Wt = g_wh + (size_t)wmat * 16384;
    int tid  = threadIdx.x;
    int row0 = blockIdx.x * 64;

    // load W tile (fp16, already [n][k]): 2048 uint4 (8 halves each)
    const uint4* Wt4 = (const uint4*)Wt;
#pragma unroll
    for (int i = 0; i < 8; i++) {
        int idx = tid + 256 * i;            // uint4 index
        int n   = idx >> 4;
        int k16 = idx & 15;
        *(uint4*)(Ws + n * S_STRIDE + k16 * 8) = Wt4[idx];
    }

    if (mode == 0) {
        // A from fp32 param, convert to fp16
#pragma unroll
        for (int i = 0; i < 8; i++) {
            int idx = tid + 256 * i;        // float4 index, 32 per row
            int r   = idx >> 5;
            int c4  = idx & 31;
            float4 v = make_float4(0.f, 0.f, 0.f, 0.f);
            if (row0 + r < N_NODES)
                v = ((const float4*)(A_in + (size_t)(row0 + r) * 128))[c4];
            __half2 h0 = __floats2half2_rn(v.x, v.y);
            __half2 h1 = __floats2half2_rn(v.z, v.w);
            unsigned int* dst = (unsigned int*)(As + r * S_STRIDE + c4 * 4);
            dst[0] = *(unsigned int*)&h0;
            dst[1] = *(unsigned int*)&h1;
        }
    } else {
        // A from g_hh fp16: straight copy, 1024 uint4
#pragma unroll
        for (int i = 0; i < 4; i++) {
            int idx = tid + 256 * i;        // uint4 index
            int r   = idx >> 4;
            int c16 = idx & 15;
            uint4 raw = make_uint4(0, 0, 0, 0);
            if (row0 + r < N_NODES)
                raw = ((const uint4*)(g_hh + (size_t)(row0 + r) * 128))[c16];
            *(uint4*)(As + r * S_STRIDE + c16 * 8) = raw;
        }
    }
    __syncthreads();

    int warp = tid >> 5, lane = tid & 31;
    int wm = warp >> 1;           // 0..3  (m groups of 16 rows)
    int wn = warp & 1;            // 0..1  (n halves of 64 cols)
    int g  = lane >> 2;           // 0..7
    int t  = lane & 3;            // 0..3

    float acc[8][4];
#pragma unroll
    for (int nt = 0; nt < 8; nt++)
#pragma unroll
        for (int c = 0; c < 4; c++) acc[nt][c] = 0.f;

    const __half* a_base = As + (wm * 16 + g) * S_STRIDE + 2 * t;
    const __half* b_base = Ws + (wn * 64 + g) * S_STRIDE + 2 * t;

#pragma unroll
    for (int ks = 0; ks < 8; ks++) {
        int kc = ks * 16;
        unsigned int a0 = *(const unsigned int*)(a_base + kc);
        unsigned int a1 = *(const unsigned int*)(a_base + 8 * S_STRIDE + kc);
        unsigned int a2 = *(const unsigned int*)(a_base + kc + 8);
        unsigned int a3 = *(const unsigned int*)(a_base + 8 * S_STRIDE + kc + 8);
#pragma unroll
        for (int nt = 0; nt < 8; nt++) {
            unsigned int b0 = *(const unsigned int*)(b_base + nt * 8 * S_STRIDE + kc);
            unsigned int b1 = *(const unsigned int*)(b_base + nt * 8 * S_STRIDE + kc + 8);
            MMA_F16(acc[nt], a0, a1, a2, a3, b0, b1);
        }
    }

    // epilogue: rows r0 = row0 + wm*16 + g, r1 = r0 + 8; cols = wn*64 + nt*8 + 2t
    int r0 = row0 + wm * 16 + g;
    int r1 = r0 + 8;
    if (mode == 0) {
#pragma unroll
        for (int nt = 0; nt < 8; nt++) {
            int col = wn * 64 + nt * 8 + 2 * t;
            float b0 = bias[col], b1 = bias[col + 1];
            if (r0 < N_NODES) {
                __half2 h = __floats2half2_rn(fmaxf(acc[nt][0] + b0, 0.f),
                                              fmaxf(acc[nt][1] + b1, 0.f));
                *(__half2*)(g_hh + (size_t)r0 * 128 + col) = h;
            }
            if (r1 < N_NODES) {
                __half2 h = __floats2half2_rn(fmaxf(acc[nt][2] + b0, 0.f),
                                              fmaxf(acc[nt][3] + b1, 0.f));
                *(__half2*)(g_hh + (size_t)r1 * 128 + col) = h;
            }
        }
    } else {
        float dv0 = (r0 < N_NODES) ? g_dinv[r0] : 0.f;
        float dv1 = (r1 < N_NODES) ? g_dinv[r1] : 0.f;
#pragma unroll
        for (int nt = 0; nt < 8; nt++) {
            int col = wn * 64 + nt * 8 + 2 * t;
            if (r0 < N_NODES) {
                __half2 h = __floats2half2_rn(acc[nt][0] * dv0, acc[nt][1] * dv0);
                *(__half2*)(g_hwh + (size_t)r0 * 128 + col) = h;
            }
            if (r1 < N_NODES) {
                __half2 h = __floats2half2_rn(acc[nt][2] * dv1, acc[nt][3] * dv1);
                *(__half2*)(g_hwh + (size_t)r1 * 128 + col) = h;
            }
        }
    }
}

// ---------------- fused aggregation + BN + ReLU (half-warp per dst node) ----------------
__global__ void __launch_bounds__(256) agg_kernel(
    const float* __restrict__ cb,
    const float* __restrict__ gamma,
    const float* __restrict__ beta,
    const float* __restrict__ mean,
    const float* __restrict__ var,
    const int* __restrict__ batch, int last)
{
    unsigned gtid = blockIdx.x * blockDim.x + threadIdx.x;
    unsigned w    = gtid >> 5;
    int lane      = threadIdx.x & 31;
    int half      = lane >> 4;
    int lane16    = lane & 15;
    unsigned n    = w * 2 + half;
    if (n >= N_NODES) return;                      // N even: whole warp exits together
    unsigned hmask = half ? 0xffff0000u : 0x0000ffffu;

    float acc[8];
    {
        uint4 raw = ((const uint4*)(g_hwh + (size_t)n * 128))[lane16];
        float2 f0 = __half22float2(*(__half2*)&raw.x);
        float2 f1 = __half22float2(*(__half2*)&raw.y);
        float2 f2 = __half22float2(*(__half2*)&raw.z);
        float2 f3 = __half22float2(*(__half2*)&raw.w);
        acc[0] = f0.x; acc[1] = f0.y; acc[2] = f1.x; acc[3] = f1.y;
        acc[4] = f2.x; acc[5] = f2.y; acc[6] = f3.x; acc[7] = f3.y;
    }

    int start = g_rowstart[n];
    int end   = g_rowstart[n + 1];
    for (int base = start; base < end; base += 16) {
        int cnt = min(16, end - base);
        int src = (base + lane16 < end) ? g_csr_src[base + lane16] : 0;
#pragma unroll 4
        for (int j = 0; j < cnt; j++) {
            int s = __shfl_sync(hmask, src, j, 16);
            uint4 raw = __ldg((const uint4*)(g_hwh + (size_t)s * 128) + lane16);
            float2 f0 = __half22float2(*(__half2*)&raw.x);
            float2 f1 = __half22float2(*(__half2*)&raw.y);
            float2 f2 = __half22float2(*(__half2*)&raw.z);
            float2 f3 = __half22float2(*(__half2*)&raw.w);
            acc[0] += f0.x; acc[1] += f0.y; acc[2] += f1.x; acc[3] += f1.y;
            acc[4] += f2.x; acc[5] += f2.y; acc[6] += f3.x; acc[7] += f3.y;
        }
    }

    float dv = g_dinv[n];
    int c8   = lane16 * 8;
    float o[8];
#pragma unroll
    for (int i = 0; i < 8; i++) {
        float s = gamma[c8 + i] * rsqrtf(var[c8 + i] + BN_EPS);
        o[i] = fmaxf((acc[i] * dv + cb[c8 + i] - mean[c8 + i]) * s + beta[c8 + i], 0.f);
    }

    if (!last) {
        __half2 h0 = __floats2half2_rn(o[0], o[1]);
        __half2 h1 = __floats2half2_rn(o[2], o[3]);
        __half2 h2 = __floats2half2_rn(o[4], o[5]);
        __half2 h3 = __floats2half2_rn(o[6], o[7]);
        uint4 st;
        st.x = *(unsigned int*)&h0; st.y = *(unsigned int*)&h1;
        st.z = *(unsigned int*)&h2; st.w = *(unsigned int*)&h3;
        *((uint4*)(g_hh + (size_t)n * 128 + c8)) = st;
    } else {
        int b = batch[n];
        float* dp = g_pool + (size_t)b * 128 + c8;
        asm volatile("red.global.add.v4.f32 [%0], {%1,%2,%3,%4};"
                     :: "l"(dp), "f"(o[0]), "f"(o[1]), "f"(o[2]), "f"(o[3]) : "memory");
        asm volatile("red.global.add.v4.f32 [%0], {%1,%2,%3,%4};"
                     :: "l"(dp + 4), "f"(o[4]), "f"(o[5]), "f"(o[6]), "f"(o[7]) : "memory");
        if (lane16 == 0) atomicAdd(&g_cnt[b], 1);
    }
}

// ---------------- MLP head: one block per graph ----------------
__global__ void mlp_kernel(const float* __restrict__ fc1w, const float* __restrict__ fc1b,
                           const float* __restrict__ fc2w, const float* __restrict__ fc2b,
                           float* __restrict__ out)
{
    __shared__ float gv[128];
    __shared__ float hid[64];
    int g = blockIdx.x;
    int t = threadIdx.x;           // 64 threads
    float cnt = fmaxf((float)g_cnt[g], 1.0f);
    float inv = 1.0f / cnt;
    gv[t]      = g_pool[g * 128 + t]      * inv;
    gv[t + 64] = g_pool[g * 128 + 64 + t] * inv;
    __syncthreads();
    float acc = fc1b[t];
#pragma unroll 8
    for (int k = 0; k < 128; k++) acc = fmaf(gv[k], fc1w[k * 64 + t], acc);
    hid[t] = fmaxf(acc, 0.f);
    __syncthreads();
    if (t < C_CLASSES) {
        float o = fc2b[t];
#pragma unroll
        for (int j = 0; j < 64; j++) o = fmaf(hid[j], fc2w[j * C_CLASSES + t], o);
        out[g * C_CLASSES + t] = o;
    }
}

__global__ void tail_kernel(float* __restrict__ out, int out_size) {
    int i = G_GRAPHS * C_CLASSES + blockIdx.x * blockDim.x + threadIdx.x;
    if (i < out_size) out[i] = 0.f;
}

// ---------------- launcher ----------------
extern "C" void kernel_launch(void* const* d_in, const int* in_sizes, int n_in,
                              void* d_out, int out_size)
{
    const float* x      = (const float*)d_in[0];
    const int*   ei     = (const int*)d_in[1];
    const int*   batch  = (const int*)d_in[2];
    const float* w_in   = (const float*)d_in[3];
    const float* b_in   = (const float*)d_in[4];
    const float* conv_w = (const float*)d_in[5];
    const float* conv_b = (const float*)d_in[6];
    const float* bn_g   = (const float*)d_in[7];
    const float* bn_b   = (const float*)d_in[8];
    const float* bn_m   = (const float*)d_in[9];
    const float* bn_v   = (const float*)d_in[10];
    const float* fc1w   = (const float*)d_in[11];
    const float* fc1b   = (const float*)d_in[12];
    const float* fc2w   = (const float*)d_in[13];
    const float* fc2b   = (const float*)d_in[14];
    float*       out    = (float*)d_out;

    const int SMEM = (128 + 64) * S_STRIDE * 2;   // 52224 B
    cudaFuncSetAttribute(gemm_kernel, cudaFuncAttributeMaxDynamicSharedMemorySize, SMEM);

    zero_kernel         <<<(N_NODES + 255) / 256, 256>>>();
    wconv_kernel        <<<(5 * 16384 + 255) / 256, 256>>>(w_in, conv_w);
    degree_kernel       <<<(E_EDGES / 4 + 255) / 256, 256>>>(ei);
    block_sum_kernel    <<<NB, 256>>>();
    scan_blocks_kernel  <<<1, 512>>>();
    fill_rowstart_kernel<<<NB, 256>>>();
    fill_csr_kernel     <<<(E_EDGES / 4 + 255) / 256, 256>>>(ei);

    // input projection (weight matrix 0)
    gemm_kernel<<<(N_NODES + 63) / 64, 256, SMEM>>>(x, 0, b_in, 0);

    // agg: half-warp per node -> N/2 warps
    const unsigned agg_blocks = (((N_NODES + 1) / 2) * 32u + 255) / 256;

    for (int l = 0; l < L_LAYERS; l++) {
        gemm_kernel<<<(N_NODES + 63) / 64, 256, SMEM>>>(nullptr, l + 1, nullptr, 1);
        agg_kernel <<<agg_blocks, 256>>>(conv_b + l * 128,
                                         bn_g + l * 128, bn_b + l * 128,
                                         bn_m + l * 128, bn_v + l * 128,
                                         batch, (l == L_LAYERS - 1) ? 1 : 0);
    }

    mlp_kernel<<<G_GRAPHS, 64>>>(fc1w, fc1b, fc2w, fc2b, out);

    int tail = out_size - G_GRAPHS * C_CLASSES;
    if (tail > 0) tail_kernel<<<(tail + 255) / 256, 256>>>(out, out_size);
}

// round 14
// speedup vs baseline: 1.7472x; 1.0421x over previous
#include <cuda_runtime.h>
#include <cuda_fp16.h>

#define N_NODES   100000
#define E_EDGES   1600000
#define H_DIM     128
#define L_LAYERS  4
#define C_CLASSES 12
#define G_GRAPHS  512
#define BN_EPS    1e-5f
#define NB        ((N_NODES + 255) / 256)   // 391 blocks

#define S_STRIDE  136   // smem stride in halves (272 B) -> conflict-free frags

#define MMA_F16(d, a0, a1, a2, a3, b0, b1) \
    asm("mma.sync.aligned.m16n8k16.row.col.f32.f16.f16.f32 " \
        "{%0,%1,%2,%3},{%4,%5,%6,%7},{%8,%9},{%0,%1,%2,%3};" \
        : "+f"((d)[0]), "+f"((d)[1]), "+f"((d)[2]), "+f"((d)[3]) \
        : "r"(a0), "r"(a1), "r"(a2), "r"(a3), "r"(b0), "r"(b1))

#define LDSM_X4(r0, r1, r2, r3, addr) \
    asm volatile("ldmatrix.sync.aligned.m8n8.x4.shared.b16 {%0,%1,%2,%3}, [%4];" \
        : "=r"(r0), "=r"(r1), "=r"(r2), "=r"(r3) : "r"(addr))

// ---------------- device scratch (no allocation allowed) ----------------
__device__ __align__(128) __half g_hh [N_NODES * H_DIM];   // activations, fp16
__device__ __align__(128) __half g_hwh[N_NODES * H_DIM];   // (h @ W) * dinv[row], fp16
__device__ __align__(128) __half g_wh [5 * H_DIM * H_DIM]; // weights, fp16, [mat][n][k]
__device__ __align__(128) float  g_dinv[N_NODES];
__device__ __align__(128) int    g_deg [N_NODES];
__device__ __align__(128) int    g_blocksum[512];
__device__ __align__(128) int    g_blockoff[512];
__device__ __align__(128) int    g_rowstart[N_NODES + 1];
__device__ __align__(128) int    g_cursor  [N_NODES];
__device__ __align__(128) int    g_csr_src [E_EDGES];
__device__ __align__(128) float  g_pool[G_GRAPHS * H_DIM];
__device__ __align__(128) int    g_cnt [G_GRAPHS];

// ---------------- preproc ----------------
// weight convert+transpose, fused with zeroing of deg/pool/cnt
__global__ void wconv_zero_kernel(const float* __restrict__ w_in,
                                  const float* __restrict__ conv_w) {
    int i = blockIdx.x * blockDim.x + threadIdx.x;     // >= max(5*16384, N_NODES)
    if (i < N_NODES)          g_deg[i] = 0;
    if (i < G_GRAPHS * H_DIM) g_pool[i] = 0.f;
    if (i < G_GRAPHS)         g_cnt[i] = 0;
    if (i < 5 * 16384) {
        int m = i >> 14;
        int r = i & 16383;
        int k = r >> 7;
        int n = r & 127;
        const float* src = (m == 0) ? w_in : conv_w + (size_t)(m - 1) * 16384;
        g_wh[(size_t)m * 16384 + n * 128 + k] = __float2half(src[k * 128 + n]);
    }
}

__global__ void degree_kernel(const int* __restrict__ ei) {
    int e4 = blockIdx.x * blockDim.x + threadIdx.x;
    if (e4 < E_EDGES / 4) {
        int4 d = ((const int4*)(ei + E_EDGES))[e4];
        atomicAdd(&g_deg[d.x], 1);
        atomicAdd(&g_deg[d.y], 1);
        atomicAdd(&g_deg[d.z], 1);
        atomicAdd(&g_deg[d.w], 1);
    }
}

// three-stage parallel exclusive scan of g_deg
__global__ void block_sum_kernel() {
    __shared__ int sd[256];
    int i = blockIdx.x * 256 + threadIdx.x;
    int v = (i < N_NODES) ? g_deg[i] : 0;
    sd[threadIdx.x] = v;
    __syncthreads();
#pragma unroll
    for (int s = 128; s > 0; s >>= 1) {
        if (threadIdx.x < s) sd[threadIdx.x] += sd[threadIdx.x + s];
        __syncthreads();
    }
    if (threadIdx.x == 0) g_blocksum[blockIdx.x] = sd[0];
}

__global__ void __launch_bounds__(512) scan_blocks_kernel() {
    __shared__ int part[512];
    int t = threadIdx.x;
    int v = (t < NB) ? g_blocksum[t] : 0;
    part[t] = v;
    __syncthreads();
#pragma unroll
    for (int d = 1; d < 512; d <<= 1) {
        int x = (t >= d) ? part[t - d] : 0;
        __syncthreads();
        part[t] += x;
        __syncthreads();
    }
    if (t < NB) g_blockoff[t] = part[t] - v;
    if (t == 511) g_rowstart[N_NODES] = part[511];
}

__global__ void fill_rowstart_kernel() {
    __shared__ int part[256];
    int i = blockIdx.x * 256 + threadIdx.x;
    int t = threadIdx.x;
    int dg = (i < N_NODES) ? g_deg[i] : 0;
    part[t] = dg;
    __syncthreads();
#pragma unroll
    for (int d = 1; d < 256; d <<= 1) {
        int x = (t >= d) ? part[t - d] : 0;
        __syncthreads();
        part[t] += x;
        __syncthreads();
    }
    if (i < N_NODES) {
        int rs = g_blockoff[blockIdx.x] + part[t] - dg;
        g_rowstart[i] = rs;
        g_cursor[i]   = rs;
        g_dinv[i]     = rsqrtf((float)dg + 1.0f);
    }
}

__global__ void fill_csr_kernel(const int* __restrict__ ei) {
    int e4 = blockIdx.x * blockDim.x + threadIdx.x;
    if (e4 < E_EDGES / 4) {
        int4 s = ((const int4*)ei)[e4];
        int4 d = ((const int4*)(ei + E_EDGES))[e4];
        g_csr_src[atomicAdd(&g_cursor[d.x], 1)] = s.x;
        g_csr_src[atomicAdd(&g_cursor[d.y], 1)] = s.y;
        g_csr_src[atomicAdd(&g_cursor[d.z], 1)] = s.z;
        g_csr_src[atomicAdd(&g_cursor[d.w], 1)] = s.w;
    }
}

// ---------------- GEMM (fp16 mma m16n8k16 + ldmatrix): [N,128] @ [128,128] ----------------
// CTA: 128 rows x 128 cols, 8 warps = 4(m) x 2(n), warp tile 32x64 (2 m-tiles).
// mode 0: g_hh  = half(relu(x @ W + bias))      (A = x param fp32)
// mode 1: g_hwh = half((g_hh @ W) * dinv[row])  (A = g_hh fp16, zero-copy)
__global__ void __launch_bounds__(256, 2) gemm_kernel(
    const float* __restrict__ A_in, int wmat,
    const float* __restrict__ bias, int mode)
{
    extern __shared__ __half smh[];
    __half* Ws = smh;                       // [n=128][k=128] stride S_STRIDE
    __half* As = smh + 128 * S_STRIDE;      // [r=128][k=128] stride S_STRIDE

    const __half* Wt = g_wh + (size_t)wmat * 16384;
    int tid  = threadIdx.x;
    int row0 = blockIdx.x * 128;

    // load W tile: 2048 uint4
    const uint4* Wt4 = (const uint4*)Wt;
#pragma unroll
    for (int i = 0; i < 8; i++) {
        int idx = tid + 256 * i;
        int n   = idx >> 4;
        int k16 = idx & 15;
        *(uint4*)(Ws + n * S_STRIDE + k16 * 8) = Wt4[idx];
    }

    if (mode == 0) {
        // A from fp32 param: 128 rows x 32 float4 = 4096 items
#pragma unroll
        for (int i = 0; i < 16; i++) {
            int idx = tid + 256 * i;
            int r   = idx >> 5;
            int c4  = idx & 31;
            float4 v = make_float4(0.f, 0.f, 0.f, 0.f);
            if (row0 + r < N_NODES)
                v = ((const float4*)(A_in + (size_t)(row0 + r) * 128))[c4];
            __half2 h0 = __floats2half2_rn(v.x, v.y);
            __half2 h1 = __floats2half2_rn(v.z, v.w);
            unsigned int* dst = (unsigned int*)(As + r * S_STRIDE + c4 * 4);
            dst[0] = *(unsigned int*)&h0;
            dst[1] = *(unsigned int*)&h1;
        }
    } else {
        // A from g_hh fp16: 128 rows x 16 uint4 = 2048 items
#pragma unroll
        for (int i = 0; i < 8; i++) {
            int idx = tid + 256 * i;
            int r   = idx >> 4;
            int c16 = idx & 15;
            uint4 raw = make_uint4(0, 0, 0, 0);
            if (row0 + r < N_NODES)
                raw = ((const uint4*)(g_hh + (size_t)(row0 + r) * 128))[c16];
            *(uint4*)(As + r * S_STRIDE + c16 * 8) = raw;
        }
    }
    __syncthreads();

    int warp = tid >> 5, lane = tid & 31;
    int wm = warp >> 1;           // 0..3  (m groups of 32 rows)
    int wn = warp & 1;            // 0..1  (n halves of 64 cols)
    int g  = lane >> 2;           // 0..7
    int t  = lane & 3;            // 0..3

    // ldmatrix lane address roles
    int lrow = lane & 7;          // row within 8x8 matrix
    int lsel = lane >> 3;         // which of the 4 matrices this lane addresses
    int rsel = (lsel & 1) * 8;    // +8 rows for matrices 1,3
    int ksel = (lsel >> 1) * 8;   // +8 k for matrices 2,3

    unsigned int a_addr0 = (unsigned int)__cvta_generic_to_shared(
        As + (wm * 32 + lrow + rsel) * S_STRIDE + ksel);
    unsigned int a_addr1 = a_addr0 + 16 * S_STRIDE * 2;   // second m-tile (+16 rows)
    unsigned int b_addr0 = (unsigned int)__cvta_generic_to_shared(
        Ws + (wn * 64 + (0 + (lsel & 1)) * 8 + lrow) * S_STRIDE + ksel);
    unsigned int b_addr1 = b_addr0 + 16 * S_STRIDE * 2;   // nt 2,3
    unsigned int b_addr2 = b_addr0 + 32 * S_STRIDE * 2;   // nt 4,5
    unsigned int b_addr3 = b_addr0 + 48 * S_STRIDE * 2;   // nt 6,7

    float acc[2][8][4];
#pragma unroll
    for (int mt = 0; mt < 2; mt++)
#pragma unroll
        for (int nt = 0; nt < 8; nt++)
#pragma unroll
            for (int c = 0; c < 4; c++) acc[mt][nt][c] = 0.f;

#pragma unroll
    for (int ks = 0; ks < 8; ks++) {
        unsigned int a0[4], a1[4];
        unsigned int b[8][2];
        unsigned int r0, r1, r2, r3;
        LDSM_X4(a0[0], a0[1], a0[2], a0[3], a_addr0);
        LDSM_X4(a1[0], a1[1], a1[2], a1[3], a_addr1);
        LDSM_X4(r0, r1, r2, r3, b_addr0);
        b[0][0] = r0; b[1][0] = r1; b[0][1] = r2; b[1][1] = r3;
        LDSM_X4(r0, r1, r2, r3, b_addr1);
        b[2][0] = r0; b[3][0] = r1; b[2][1] = r2; b[3][1] = r3;
        LDSM_X4(r0, r1, r2, r3, b_addr2);
        b[4][0] = r0; b[5][0] = r1; b[4][1] = r2; b[5][1] = r3;
        LDSM_X4(r0, r1, r2, r3, b_addr3);
        b[6][0] = r0; b[7][0] = r1; b[6][1] = r2; b[7][1] = r3;
#pragma unroll
        for (int nt = 0; nt < 8; nt++) {
            MMA_F16(acc[0][nt], a0[0], a0[1], a0[2], a0[3], b[nt][0], b[nt][1]);
            MMA_F16(acc[1][nt], a1[0], a1[1], a1[2], a1[3], b[nt][0], b[nt][1]);
        }
        a_addr0 += 32; a_addr1 += 32;                    // +16 halves of k
        b_addr0 += 32; b_addr1 += 32; b_addr2 += 32; b_addr3 += 32;
    }

    // epilogue
#pragma unroll
    for (int mt = 0; mt < 2; mt++) {
        int r0 = row0 + wm * 32 + mt * 16 + g;
        int r1 = r0 + 8;
        if (mode == 0) {
#pragma unroll
            for (int nt = 0; nt < 8; nt++) {
                int col = wn * 64 + nt * 8 + 2 * t;
                float b0 = bias[col], b1 = bias[col + 1];
                if (r0 < N_NODES) {
                    __half2 h = __floats2half2_rn(fmaxf(acc[mt][nt][0] + b0, 0.f),
                                                  fmaxf(acc[mt][nt][1] + b1, 0.f));
                    *(__half2*)(g_hh + (size_t)r0 * 128 + col) = h;
                }
                if (r1 < N_NODES) {
                    __half2 h = __floats2half2_rn(fmaxf(acc[mt][nt][2] + b0, 0.f),
                                                  fmaxf(acc[mt][nt][3] + b1, 0.f));
                    *(__half2*)(g_hh + (size_t)r1 * 128 + col) = h;
                }
            }
        } else {
            float dv0 = (r0 < N_NODES) ? g_dinv[r0] : 0.f;
            float dv1 = (r1 < N_NODES) ? g_dinv[r1] : 0.f;
#pragma unroll
            for (int nt = 0; nt < 8; nt++) {
                int col = wn * 64 + nt * 8 + 2 * t;
                if (r0 < N_NODES) {
                    __half2 h = __floats2half2_rn(acc[mt][nt][0] * dv0, acc[mt][nt][1] * dv0);
                    *(__half2*)(g_hwh + (size_t)r0 * 128 + col) = h;
                }
                if (r1 < N_NODES) {
                    __half2 h = __floats2half2_rn(acc[mt][nt][2] * dv1, acc[mt][nt][3] * dv1);
                    *(__half2*)(g_hwh + (size_t)r1 * 128 + col) = h;
                }
            }
        }
    }
}

// ---------------- fused aggregation + BN + ReLU (half-warp per dst node) ----------------
__global__ void __launch_bounds__(256) agg_kernel(
    const float* __restrict__ cb,
    const float* __restrict__ gamma,
    const float* __restrict__ beta,
    const float* __restrict__ mean,
    const float* __restrict__ var,
    const int* __restrict__ batch, int last)
{
    unsigned gtid = blockIdx.x * blockDim.x + threadIdx.x;
    unsigned w    = gtid >> 5;
    int lane      = threadIdx.x & 31;
    int half      = lane >> 4;
    int lane16    = lane & 15;
    unsigned n    = w * 2 + half;
    if (n >= N_NODES) return;                      // N even: whole warp exits together
    unsigned hmask = half ? 0xffff0000u : 0x0000ffffu;

    float acc[8];
    {
        uint4 raw = ((const uint4*)(g_hwh + (size_t)n * 128))[lane16];
        float2 f0 = __half22float2(*(__half2*)&raw.x);
        float2 f1 = __half22float2(*(__half2*)&raw.y);
        float2 f2 = __half22float2(*(__half2*)&raw.z);
        float2 f3 = __half22float2(*(__half2*)&raw.w);
        acc[0] = f0.x; acc[1] = f0.y; acc[2] = f1.x; acc[3] = f1.y;
        acc[4] = f2.x; acc[5] = f2.y; acc[6] = f3.x; acc[7] = f3.y;
    }

    int start = g_rowstart[n];
    int end   = g_rowstart[n + 1];
    for (int base = start; base < end; base += 16) {
        int cnt = min(16, end - base);
        int src = (base + lane16 < end) ? g_csr_src[base + lane16] : 0;
#pragma unroll 4
        for (int j = 0; j < cnt; j++) {
            int s = __shfl_sync(hmask, src, j, 16);
            uint4 raw = __ldg((const uint4*)(g_hwh + (size_t)s * 128) + lane16);
            float2 f0 = __half22float2(*(__half2*)&raw.x);
            float2 f1 = __half22float2(*(__half2*)&raw.y);
            float2 f2 = __half22float2(*(__half2*)&raw.z);
            float2 f3 = __half22float2(*(__half2*)&raw.w);
            acc[0] += f0.x; acc[1] += f0.y; acc[2] += f1.x; acc[3] += f1.y;
            acc[4] += f2.x; acc[5] += f2.y; acc[6] += f3.x; acc[7] += f3.y;
        }
    }

    float dv = g_dinv[n];
    int c8   = lane16 * 8;
    float o[8];
#pragma unroll
    for (int i = 0; i < 8; i++) {
        float s = gamma[c8 + i] * rsqrtf(var[c8 + i] + BN_EPS);
        o[i] = fmaxf((acc[i] * dv + cb[c8 + i] - mean[c8 + i]) * s + beta[c8 + i], 0.f);
    }

    if (!last) {
        __half2 h0 = __floats2half2_rn(o[0], o[1]);
        __half2 h1 = __floats2half2_rn(o[2], o[3]);
        __half2 h2 = __floats2half2_rn(o[4], o[5]);
        __half2 h3 = __floats2half2_rn(o[6], o[7]);
        uint4 st;
        st.x = *(unsigned int*)&h0; st.y = *(unsigned int*)&h1;
        st.z = *(unsigned int*)&h2; st.w = *(unsigned int*)&h3;
        *((uint4*)(g_hh + (size_t)n * 128 + c8)) = st;
    } else {
        int b = batch[n];
        float* dp = g_pool + (size_t)b * 128 + c8;
        asm volatile("red.global.add.v4.f32 [%0], {%1,%2,%3,%4};"
                     :: "l"(dp), "f"(o[0]), "f"(o[1]), "f"(o[2]), "f"(o[3]) : "memory");
        asm volatile("red.global.add.v4.f32 [%0], {%1,%2,%3,%4};"
                     :: "l"(dp + 4), "f"(o[4]), "f"(o[5]), "f"(o[6]), "f"(o[7]) : "memory");
        if (lane16 == 0) atomicAdd(&g_cnt[b], 1);
    }
}

// ---------------- MLP head: one block per graph ----------------
__global__ void mlp_kernel(const float* __restrict__ fc1w, const float* __restrict__ fc1b,
                           const float* __restrict__ fc2w, const float* __restrict__ fc2b,
                           float* __restrict__ out)
{
    __shared__ float gv[128];
    __shared__ float hid[64];
    int g = blockIdx.x;
    int t = threadIdx.x;           // 64 threads
    float cnt = fmaxf((float)g_cnt[g], 1.0f);
    float inv = 1.0f / cnt;
    gv[t]      = g_pool[g * 128 + t]      * inv;
    gv[t + 64] = g_pool[g * 128 + 64 + t] * inv;
    __syncthreads();
    float acc = fc1b[t];
#pragma unroll 8
    for (int k = 0; k < 128; k++) acc = fmaf(gv[k], fc1w[k * 64 + t], acc);
    hid[t] = fmaxf(acc, 0.f);
    __syncthreads();
    if (t < C_CLASSES) {
        float o = fc2b[t];
#pragma unroll
        for (int j = 0; j < 64; j++) o = fmaf(hid[j], fc2w[j * C_CLASSES + t], o);
        out[g * C_CLASSES + t] = o;
    }
}

__global__ void tail_kernel(float* __restrict__ out, int out_size) {
    int i = G_GRAPHS * C_CLASSES + blockIdx.x * blockDim.x + threadIdx.x;
    if (i < out_size) out[i] = 0.f;
}

// ---------------- launcher ----------------
extern "C" void kernel_launch(void* const* d_in, const int* in_sizes, int n_in,
                              void* d_out, int out_size)
{
    const float* x      = (const float*)d_in[0];
    const int*   ei     = (const int*)d_in[1];
    const int*   batch  = (const int*)d_in[2];
    const float* w_in   = (const float*)d_in[3];
    const float* b_in   = (const float*)d_in[4];
    const float* conv_w = (const float*)d_in[5];
    const float* conv_b = (const float*)d_in[6];
    const float* bn_g   = (const float*)d_in[7];
    const float* bn_b   = (const float*)d_in[8];
    const float* bn_m   = (const float*)d_in[9];
    const float* bn_v   = (const float*)d_in[10];
    const float* fc1w   = (const float*)d_in[11];
    const float* fc1b   = (const float*)d_in[12];
    const float* fc2w   = (const float*)d_in[13];
    const float* fc2b   = (const float*)d_in[14];
    float*       out    = (float*)d_out;

    const int SMEM = 256 * S_STRIDE * 2;   // 69632 B (W 128 rows + A 128 rows)
    cudaFuncSetAttribute(gemm_kernel, cudaFuncAttributeMaxDynamicSharedMemorySize, SMEM);

    wconv_zero_kernel   <<<(N_NODES + 255) / 256, 256>>>(w_in, conv_w);
    degree_kernel       <<<(E_EDGES / 4 + 255) / 256, 256>>>(ei);
    block_sum_kernel    <<<NB, 256>>>();
    scan_blocks_kernel  <<<1, 512>>>();
    fill_rowstart_kernel<<<NB, 256>>>();
    fill_csr_kernel     <<<(E_EDGES / 4 + 255) / 256, 256>>>(ei);

    // input projection (weight matrix 0)
    gemm_kernel<<<(N_NODES + 127) / 128, 256, SMEM>>>(x, 0, b_in, 0);

    // agg: half-warp per node -> N/2 warps
    const unsigned agg_blocks = (((N_NODES + 1) / 2) * 32u + 255) / 256;

    for (int l = 0; l < L_LAYERS; l++) {
        gemm_kernel<<<(N_NODES + 127) / 128, 256, SMEM>>>(nullptr, l + 1, nullptr, 1);
        agg_kernel <<<agg_blocks, 256>>>(conv_b + l * 128,
                                         bn_g + l * 128, bn_b + l * 128,
                                         bn_m + l * 128, bn_v + l * 128,
                                         batch, (l == L_LAYERS - 1) ? 1 : 0);
    }

    mlp_kernel<<<G_GRAPHS, 64>>>(fc1w, fc1b, fc2w, fc2b, out);

    int tail = out_size - G_GRAPHS * C_CLASSES;
    if (tail > 0) tail_kernel<<<(tail + 255) / 256, 256>>>(out, out_size);
}

// round 15
// speedup vs baseline: 1.7943x; 1.0270x over previous
#include <cuda_runtime.h>
#include <cuda_fp16.h>

#define N_NODES   100000
#define E_EDGES   1600000
#define H_DIM     128
#define L_LAYERS  4
#define C_CLASSES 12
#define G_GRAPHS  512
#define BN_EPS    1e-5f
#define NB        ((N_NODES + 255) / 256)   // 391 blocks

#define S_STRIDE  136   // smem stride in halves (272 B) -> conflict-free frags

#define MMA_F16(d, a0, a1, a2, a3, b0, b1) \
    asm("mma.sync.aligned.m16n8k16.row.col.f32.f16.f16.f32 " \
        "{%0,%1,%2,%3},{%4,%5,%6,%7},{%8,%9},{%0,%1,%2,%3};" \
        : "+f"((d)[0]), "+f"((d)[1]), "+f"((d)[2]), "+f"((d)[3]) \
        : "r"(a0), "r"(a1), "r"(a2), "r"(a3), "r"(b0), "r"(b1))

#define LDSM_X4(r0, r1, r2, r3, addr) \
    asm volatile("ldmatrix.sync.aligned.m8n8.x4.shared.b16 {%0,%1,%2,%3}, [%4];" \
        : "=r"(r0), "=r"(r1), "=r"(r2), "=r"(r3) : "r"(addr))

// ---------------- device scratch (no allocation allowed) ----------------
__device__ __align__(128) __half g_hh [N_NODES * H_DIM];   // activations, fp16
__device__ __align__(128) __half g_hwh[N_NODES * H_DIM];   // (h @ W) * dinv[row], fp16
__device__ __align__(128) __half g_wh [5 * H_DIM * H_DIM]; // weights, fp16, [mat][n][k]
__device__ __align__(128) float  g_dinv[N_NODES];
__device__ __align__(128) int    g_deg [N_NODES];
__device__ __align__(128) int    g_blocksum[512];
__device__ __align__(128) int    g_blockoff[512];
__device__ __align__(128) int    g_rowstart[N_NODES + 1];
__device__ __align__(128) int    g_cursor  [N_NODES];
__device__ __align__(128) int    g_csr_src [E_EDGES];
__device__ __align__(128) float  g_pool[G_GRAPHS * H_DIM];
__device__ __align__(128) int    g_cnt [G_GRAPHS];

// ---------------- preproc ----------------
// weight convert+transpose, fused with zeroing of deg/pool/cnt
__global__ void wconv_zero_kernel(const float* __restrict__ w_in,
                                  const float* __restrict__ conv_w) {
    int i = blockIdx.x * blockDim.x + threadIdx.x;     // >= max(5*16384, N_NODES)
    if (i < N_NODES)          g_deg[i] = 0;
    if (i < G_GRAPHS * H_DIM) g_pool[i] = 0.f;
    if (i < G_GRAPHS)         g_cnt[i] = 0;
    if (i < 5 * 16384) {
        int m = i >> 14;
        int r = i & 16383;
        int k = r >> 7;
        int n = r & 127;
        const float* src = (m == 0) ? w_in : conv_w + (size_t)(m - 1) * 16384;
        g_wh[(size_t)m * 16384 + n * 128 + k] = __float2half(src[k * 128 + n]);
    }
}

__global__ void degree_kernel(const int* __restrict__ ei) {
    int e4 = blockIdx.x * blockDim.x + threadIdx.x;
    if (e4 < E_EDGES / 4) {
        int4 d = ((const int4*)(ei + E_EDGES))[e4];
        atomicAdd(&g_deg[d.x], 1);
        atomicAdd(&g_deg[d.y], 1);
        atomicAdd(&g_deg[d.z], 1);
        atomicAdd(&g_deg[d.w], 1);
    }
}

// three-stage parallel exclusive scan of g_deg
__global__ void block_sum_kernel() {
    __shared__ int sd[256];
    int i = blockIdx.x * 256 + threadIdx.x;
    int v = (i < N_NODES) ? g_deg[i] : 0;
    sd[threadIdx.x] = v;
    __syncthreads();
#pragma unroll
    for (int s = 128; s > 0; s >>= 1) {
        if (threadIdx.x < s) sd[threadIdx.x] += sd[threadIdx.x + s];
        __syncthreads();
    }
    if (threadIdx.x == 0) g_blocksum[blockIdx.x] = sd[0];
}

__global__ void __launch_bounds__(512) scan_blocks_kernel() {
    __shared__ int part[512];
    int t = threadIdx.x;
    int v = (t < NB) ? g_blocksum[t] : 0;
    part[t] = v;
    __syncthreads();
#pragma unroll
    for (int d = 1; d < 512; d <<= 1) {
        int x = (t >= d) ? part[t - d] : 0;
        __syncthreads();
        part[t] += x;
        __syncthreads();
    }
    if (t < NB) g_blockoff[t] = part[t] - v;
    if (t == 511) g_rowstart[N_NODES] = part[511];
}

__global__ void fill_rowstart_kernel() {
    __shared__ int part[256];
    int i = blockIdx.x * 256 + threadIdx.x;
    int t = threadIdx.x;
    int dg = (i < N_NODES) ? g_deg[i] : 0;
    part[t] = dg;
    __syncthreads();
#pragma unroll
    for (int d = 1; d < 256; d <<= 1) {
        int x = (t >= d) ? part[t - d] : 0;
        __syncthreads();
        part[t] += x;
        __syncthreads();
    }
    if (i < N_NODES) {
        int rs = g_blockoff[blockIdx.x] + part[t] - dg;
        g_rowstart[i] = rs;
        g_cursor[i]   = rs;
        g_dinv[i]     = rsqrtf((float)dg + 1.0f);
    }
}

__global__ void fill_csr_kernel(const int* __restrict__ ei) {
    int e4 = blockIdx.x * blockDim.x + threadIdx.x;
    if (e4 < E_EDGES / 4) {
        int4 s = ((const int4*)ei)[e4];
        int4 d = ((const int4*)(ei + E_EDGES))[e4];
        g_csr_src[atomicAdd(&g_cursor[d.x], 1)] = s.x;
        g_csr_src[atomicAdd(&g_cursor[d.y], 1)] = s.y;
        g_csr_src[atomicAdd(&g_cursor[d.z], 1)] = s.z;
        g_csr_src[atomicAdd(&g_cursor[d.w], 1)] = s.w;
    }
}

// ---------------- GEMM (fp16 mma m16n8k16 + ldmatrix): [N,128] @ [128,128] ----------------
// CTA: 128 rows x 128 cols, 8 warps = 4(m) x 2(n), warp tile 32x64 (2 m-tiles).
// mode 0: g_hh  = half(relu(x @ W + bias))      (A = x param fp32)
// mode 1: g_hwh = half((g_hh @ W) * dinv[row])  (A = g_hh fp16, zero-copy)
__global__ void __launch_bounds__(256, 2) gemm_kernel(
    const float* __restrict__ A_in, int wmat,
    const float* __restrict__ bias, int mode)
{
    extern __shared__ __half smh[];
    __half* Ws = smh;                       // [n=128][k=128] stride S_STRIDE
    __half* As = smh + 128 * S_STRIDE;      // [r=128][k=128] stride S_STRIDE

    const __half* Wt = g_wh + (size_t)wmat * 16384;
    int tid  = threadIdx.x;
    int row0 = blockIdx.x * 128;

    // load W tile: 2048 uint4
    const uint4* Wt4 = (const uint4*)Wt;
#pragma unroll
    for (int i = 0; i < 8; i++) {
        int idx = tid + 256 * i;
        int n   = idx >> 4;
        int k16 = idx & 15;
        *(uint4*)(Ws + n * S_STRIDE + k16 * 8) = Wt4[idx];
    }

    if (mode == 0) {
        // A from fp32 param: 128 rows x 32 float4 = 4096 items
#pragma unroll
        for (int i = 0; i < 16; i++) {
            int idx = tid + 256 * i;
            int r   = idx >> 5;
            int c4  = idx & 31;
            float4 v = make_float4(0.f, 0.f, 0.f, 0.f);
            if (row0 + r < N_NODES)
                v = ((const float4*)(A_in + (size_t)(row0 + r) * 128))[c4];
            __half2 h0 = __floats2half2_rn(v.x, v.y);
            __half2 h1 = __floats2half2_rn(v.z, v.w);
            unsigned int* dst = (unsigned int*)(As + r * S_STRIDE + c4 * 4);
            dst[0] = *(unsigned int*)&h0;
            dst[1] = *(unsigned int*)&h1;
        }
    } else {
        // A from g_hh fp16: 128 rows x 16 uint4 = 2048 items
#pragma unroll
        for (int i = 0; i < 8; i++) {
            int idx = tid + 256 * i;
            int r   = idx >> 4;
            int c16 = idx & 15;
            uint4 raw = make_uint4(0, 0, 0, 0);
            if (row0 + r < N_NODES)
                raw = ((const uint4*)(g_hh + (size_t)(row0 + r) * 128))[c16];
            *(uint4*)(As + r * S_STRIDE + c16 * 8) = raw;
        }
    }
    __syncthreads();

    int warp = tid >> 5, lane = tid & 31;
    int wm = warp >> 1;           // 0..3  (m groups of 32 rows)
    int wn = warp & 1;            // 0..1  (n halves of 64 cols)
    int g  = lane >> 2;           // 0..7
    int t  = lane & 3;            // 0..3

    // ldmatrix lane address roles
    int lrow = lane & 7;
    int lsel = lane >> 3;
    int rsel = (lsel & 1) * 8;
    int ksel = (lsel >> 1) * 8;

    unsigned int a_addr0 = (unsigned int)__cvta_generic_to_shared(
        As + (wm * 32 + lrow + rsel) * S_STRIDE + ksel);
    unsigned int a_addr1 = a_addr0 + 16 * S_STRIDE * 2;
    unsigned int b_addr0 = (unsigned int)__cvta_generic_to_shared(
        Ws + (wn * 64 + (lsel & 1) * 8 + lrow) * S_STRIDE + ksel);
    unsigned int b_addr1 = b_addr0 + 16 * S_STRIDE * 2;
    unsigned int b_addr2 = b_addr0 + 32 * S_STRIDE * 2;
    unsigned int b_addr3 = b_addr0 + 48 * S_STRIDE * 2;

    float acc[2][8][4];
#pragma unroll
    for (int mt = 0; mt < 2; mt++)
#pragma unroll
        for (int nt = 0; nt < 8; nt++)
#pragma unroll
            for (int c = 0; c < 4; c++) acc[mt][nt][c] = 0.f;

#pragma unroll
    for (int ks = 0; ks < 8; ks++) {
        unsigned int a0[4], a1[4];
        unsigned int b[8][2];
        unsigned int r0, r1, r2, r3;
        LDSM_X4(a0[0], a0[1], a0[2], a0[3], a_addr0);
        LDSM_X4(a1[0], a1[1], a1[2], a1[3], a_addr1);
        LDSM_X4(r0, r1, r2, r3, b_addr0);
        b[0][0] = r0; b[1][0] = r1; b[0][1] = r2; b[1][1] = r3;
        LDSM_X4(r0, r1, r2, r3, b_addr1);
        b[2][0] = r0; b[3][0] = r1; b[2][1] = r2; b[3][1] = r3;
        LDSM_X4(r0, r1, r2, r3, b_addr2);
        b[4][0] = r0; b[5][0] = r1; b[4][1] = r2; b[5][1] = r3;
        LDSM_X4(r0, r1, r2, r3, b_addr3);
        b[6][0] = r0; b[7][0] = r1; b[6][1] = r2; b[7][1] = r3;
#pragma unroll
        for (int nt = 0; nt < 8; nt++) {
            MMA_F16(acc[0][nt], a0[0], a0[1], a0[2], a0[3], b[nt][0], b[nt][1]);
            MMA_F16(acc[1][nt], a1[0], a1[1], a1[2], a1[3], b[nt][0], b[nt][1]);
        }
        a_addr0 += 32; a_addr1 += 32;
        b_addr0 += 32; b_addr1 += 32; b_addr2 += 32; b_addr3 += 32;
    }

    // epilogue
#pragma unroll
    for (int mt = 0; mt < 2; mt++) {
        int r0 = row0 + wm * 32 + mt * 16 + g;
        int r1 = r0 + 8;
        if (mode == 0) {
#pragma unroll
            for (int nt = 0; nt < 8; nt++) {
                int col = wn * 64 + nt * 8 + 2 * t;
                float b0 = bias[col], b1 = bias[col + 1];
                if (r0 < N_NODES) {
                    __half2 h = __floats2half2_rn(fmaxf(acc[mt][nt][0] + b0, 0.f),
                                                  fmaxf(acc[mt][nt][1] + b1, 0.f));
                    *(__half2*)(g_hh + (size_t)r0 * 128 + col) = h;
                }
                if (r1 < N_NODES) {
                    __half2 h = __floats2half2_rn(fmaxf(acc[mt][nt][2] + b0, 0.f),
                                                  fmaxf(acc[mt][nt][3] + b1, 0.f));
                    *(__half2*)(g_hh + (size_t)r1 * 128 + col) = h;
                }
            }
        } else {
            float dv0 = (r0 < N_NODES) ? g_dinv[r0] : 0.f;
            float dv1 = (r1 < N_NODES) ? g_dinv[r1] : 0.f;
#pragma unroll
            for (int nt = 0; nt < 8; nt++) {
                int col = wn * 64 + nt * 8 + 2 * t;
                if (r0 < N_NODES) {
                    __half2 h = __floats2half2_rn(acc[mt][nt][0] * dv0, acc[mt][nt][1] * dv0);
                    *(__half2*)(g_hwh + (size_t)r0 * 128 + col) = h;
                }
                if (r1 < N_NODES) {
                    __half2 h = __floats2half2_rn(acc[mt][nt][2] * dv1, acc[mt][nt][3] * dv1);
                    *(__half2*)(g_hwh + (size_t)r1 * 128 + col) = h;
                }
            }
        }
    }
}

// ---------------- fused aggregation + BN + ReLU (half-warp per dst node) ----------------
__global__ void __launch_bounds__(256) agg_kernel(
    const float* __restrict__ cb,
    const float* __restrict__ gamma,
    const float* __restrict__ beta,
    const float* __restrict__ mean,
    const float* __restrict__ var,
    const int* __restrict__ batch, int last)
{
    unsigned gtid = blockIdx.x * blockDim.x + threadIdx.x;
    unsigned w    = gtid >> 5;
    int lane      = threadIdx.x & 31;
    int half      = lane >> 4;
    int lane16    = lane & 15;
    unsigned n    = w * 2 + half;
    if (n >= N_NODES) return;                      // N even: whole warp exits together
    unsigned hmask = half ? 0xffff0000u : 0x0000ffffu;

    float acc[8];
    {
        uint4 raw = ((const uint4*)(g_hwh + (size_t)n * 128))[lane16];
        float2 f0 = __half22float2(*(__half2*)&raw.x);
        float2 f1 = __half22float2(*(__half2*)&raw.y);
        float2 f2 = __half22float2(*(__half2*)&raw.z);
        float2 f3 = __half22float2(*(__half2*)&raw.w);
        acc[0] = f0.x; acc[1] = f0.y; acc[2] = f1.x; acc[3] = f1.y;
        acc[4] = f2.x; acc[5] = f2.y; acc[6] = f3.x; acc[7] = f3.y;
    }

    int start = g_rowstart[n];
    int end   = g_rowstart[n + 1];
    for (int base = start; base < end; base += 16) {
        int cnt = min(16, end - base);
        int src = (base + lane16 < end) ? g_csr_src[base + lane16] : 0;
#pragma unroll 4
        for (int j = 0; j < cnt; j++) {
            int s = __shfl_sync(hmask, src, j, 16);
            uint4 raw = __ldg((const uint4*)(g_hwh + (size_t)s * 128) + lane16);
            float2 f0 = __half22float2(*(__half2*)&raw.x);
            float2 f1 = __half22float2(*(__half2*)&raw.y);
            float2 f2 = __half22float2(*(__half2*)&raw.z);
            float2 f3 = __half22float2(*(__half2*)&raw.w);
            acc[0] += f0.x; acc[1] += f0.y; acc[2] += f1.x; acc[3] += f1.y;
            acc[4] += f2.x; acc[5] += f2.y; acc[6] += f3.x; acc[7] += f3.y;
        }
    }

    float dv = g_dinv[n];
    int c8   = lane16 * 8;
    float o[8];
#pragma unroll
    for (int i = 0; i < 8; i++) {
        float s = gamma[c8 + i] * rsqrtf(var[c8 + i] + BN_EPS);
        o[i] = fmaxf((acc[i] * dv + cb[c8 + i] - mean[c8 + i]) * s + beta[c8 + i], 0.f);
    }

    if (!last) {
        __half2 h0 = __floats2half2_rn(o[0], o[1]);
        __half2 h1 = __floats2half2_rn(o[2], o[3]);
        __half2 h2 = __floats2half2_rn(o[4], o[5]);
        __half2 h3 = __floats2half2_rn(o[6], o[7]);
        uint4 st;
        st.x = *(unsigned int*)&h0; st.y = *(unsigned int*)&h1;
        st.z = *(unsigned int*)&h2; st.w = *(unsigned int*)&h3;
        *((uint4*)(g_hh + (size_t)n * 128 + c8)) = st;
    } else {
        int b = batch[n];
        float* dp = g_pool + (size_t)b * 128 + c8;
        asm volatile("red.global.add.v4.f32 [%0], {%1,%2,%3,%4};"
                     :: "l"(dp), "f"(o[0]), "f"(o[1]), "f"(o[2]), "f"(o[3]) : "memory");
        asm volatile("red.global.add.v4.f32 [%0], {%1,%2,%3,%4};"
                     :: "l"(dp + 4), "f"(o[4]), "f"(o[5]), "f"(o[6]), "f"(o[7]) : "memory");
        if (lane16 == 0) atomicAdd(&g_cnt[b], 1);
    }
}

// ---------------- MLP head: one block per graph ----------------
__global__ void mlp_kernel(const float* __restrict__ fc1w, const float* __restrict__ fc1b,
                           const float* __restrict__ fc2w, const float* __restrict__ fc2b,
                           float* __restrict__ out)
{
    __shared__ float gv[128];
    __shared__ float hid[64];
    int g = blockIdx.x;
    int t = threadIdx.x;           // 64 threads
    float cnt = fmaxf((float)g_cnt[g], 1.0f);
    float inv = 1.0f / cnt;
    gv[t]      = g_pool[g * 128 + t]      * inv;
    gv[t + 64] = g_pool[g * 128 + 64 + t] * inv;
    __syncthreads();
    float acc = fc1b[t];
#pragma unroll 8
    for (int k = 0; k < 128; k++) acc = fmaf(gv[k], fc1w[k * 64 + t], acc);
    hid[t] = fmaxf(acc, 0.f);
    __syncthreads();
    if (t < C_CLASSES) {
        float o = fc2b[t];
#pragma unroll
        for (int j = 0; j < 64; j++) o = fmaf(hid[j], fc2w[j * C_CLASSES + t], o);
        out[g * C_CLASSES + t] = o;
    }
}

__global__ void tail_kernel(float* __restrict__ out, int out_size) {
    int i = G_GRAPHS * C_CLASSES + blockIdx.x * blockDim.x + threadIdx.x;
    if (i < out_size) out[i] = 0.f;
}

// ---------------- launcher ----------------
extern "C" void kernel_launch(void* const* d_in, const int* in_sizes, int n_in,
                              void* d_out, int out_size)
{
    const float* x      = (const float*)d_in[0];
    const int*   ei     = (const int*)d_in[1];
    const int*   batch  = (const int*)d_in[2];
    const float* w_in   = (const float*)d_in[3];
    const float* b_in   = (const float*)d_in[4];
    const float* conv_w = (const float*)d_in[5];
    const float* conv_b = (const float*)d_in[6];
    const float* bn_g   = (const float*)d_in[7];
    const float* bn_b   = (const float*)d_in[8];
    const float* bn_m   = (const float*)d_in[9];
    const float* bn_v   = (const float*)d_in[10];
    const float* fc1w   = (const float*)d_in[11];
    const float* fc1b   = (const float*)d_in[12];
    const float* fc2w   = (const float*)d_in[13];
    const float* fc2b   = (const float*)d_in[14];
    float*       out    = (float*)d_out;

    const int SMEM = 256 * S_STRIDE * 2;   // 69632 B (W 128 rows + A 128 rows)
    cudaFuncSetAttribute(gemm_kernel, cudaFuncAttributeMaxDynamicSharedMemorySize, SMEM);

    // persistent side stream + events (host objects; created once, device work
    // per call is identical -> deterministic)
    static cudaStream_t s1 = nullptr;
    static cudaEvent_t evFork = nullptr, evRow = nullptr, evCsr = nullptr;
    if (s1 == nullptr) {
        cudaStreamCreateWithFlags(&s1, cudaStreamNonBlocking);
        cudaEventCreateWithFlags(&evFork, cudaEventDisableTiming);
        cudaEventCreateWithFlags(&evRow,  cudaEventDisableTiming);
        cudaEventCreateWithFlags(&evCsr,  cudaEventDisableTiming);
    }

    // stage 0: weight convert + zero (everything depends on this)
    wconv_zero_kernel<<<(N_NODES + 255) / 256, 256>>>(w_in, conv_w);

    // fork: CSR build chain on s1, GEMMs on the main stream
    cudaEventRecord(evFork, 0);
    cudaStreamWaitEvent(s1, evFork, 0);

    int tail = out_size - G_GRAPHS * C_CLASSES;
    if (tail > 0) tail_kernel<<<(tail + 255) / 256, 256, 0, s1>>>(out, out_size);
    degree_kernel       <<<(E_EDGES / 4 + 255) / 256, 256, 0, s1>>>(ei);
    block_sum_kernel    <<<NB, 256, 0, s1>>>();
    scan_blocks_kernel  <<<1, 512, 0, s1>>>();
    fill_rowstart_kernel<<<NB, 256, 0, s1>>>();
    cudaEventRecord(evRow, s1);                 // dinv/rowstart ready
    fill_csr_kernel     <<<(E_EDGES / 4 + 255) / 256, 256, 0, s1>>>(ei);
    cudaEventRecord(evCsr, s1);                 // CSR ready

    // main stream: input projection (independent of CSR chain)
    gemm_kernel<<<(N_NODES + 127) / 128, 256, SMEM>>>(x, 0, b_in, 0);

    // gemm mode-1 needs dinv
    cudaStreamWaitEvent(0, evRow, 0);
    // agg needs CSR
    const unsigned agg_blocks = (((N_NODES + 1) / 2) * 32u + 255) / 256;

    for (int l = 0; l < L_LAYERS; l++) {
        gemm_kernel<<<(N_NODES + 127) / 128, 256, SMEM>>>(nullptr, l + 1, nullptr, 1);
        if (l == 0) cudaStreamWaitEvent(0, evCsr, 0);
        agg_kernel <<<agg_blocks, 256>>>(conv_b + l * 128,
                                         bn_g + l * 128, bn_b + l * 128,
                                         bn_m + l * 128, bn_v + l * 128,
                                         batch, (l == L_LAYERS - 1) ? 1 : 0);
    }

    mlp_kernel<<<G_GRAPHS, 64>>>(fc1w, fc1b, fc2w, fc2b, out);
}